// round 3
// baseline (speedup 1.0000x reference)
#include <cuda_runtime.h>
#include <math.h>
#include <stdint.h>

// Problem constants
#define Bz 64
#define Tz 512
#define Cz 512
#define Hz 512
#define Gz 2048   // 4*H
#define Mz (Bz*Tz) // 32768
#define NBLK 128

// ---------------- device scratch (static, no allocation) ----------------
__device__ float g_xp[(size_t)Mz * Gz];      // [m][g], m = b*T+t   (256 MB)
__device__ float g_hseq[(size_t)Mz * Hz];    // [m][c]              (64 MB)
__device__ float g_h0[Hz * Bz];              // h buffer [k][b]
__device__ float g_h1[Hz * Bz];
__device__ float g_wt1[Cz * Gz];             // W_ih1 transposed [c][g]
__device__ float g_wt2[Hz * Gz];             // W_ih2 transposed [c][g]
__device__ float g_bias1[Gz];
__device__ float g_bias2[Gz];
__device__ unsigned long long g_flag[NBLK];  // per-block barrier flags (monotonic)

// ---------------- prep: transpose W_ih, fold biases ----------------
__global__ void lstm_prep(const float* __restrict__ Wih1,
                          const float* __restrict__ bih1,
                          const float* __restrict__ bhh1,
                          const float* __restrict__ Wih2,
                          const float* __restrict__ bih2,
                          const float* __restrict__ bhh2)
{
    int i = blockIdx.x * blockDim.x + threadIdx.x;
    if (i < Cz * Gz) {
        int g = i / Cz;
        int c = i - g * Cz;
        g_wt1[(size_t)c * Gz + g] = Wih1[(size_t)g * Cz + c];
        g_wt2[(size_t)c * Gz + g] = Wih2[(size_t)g * Cz + c];
    }
    if (i < Gz) {
        g_bias1[i] = bih1[i] + bhh1[i];
        g_bias2[i] = bih2[i] + bhh2[i];
    }
}

// ---------------- xp GEMM: C[m][g] = sum_c A[m][c]*Wt[c][g] + bias[g] ---
template<bool XLAYOUT>
__global__ void __launch_bounds__(256)
gemm_xp(const float* __restrict__ A,
        const float* __restrict__ Wt,
        const float* __restrict__ bias,
        float* __restrict__ Cout)
{
    __shared__ float As[16][128];
    __shared__ float Bs[16][128];

    const int m0 = blockIdx.y * 128;
    const int g0 = blockIdx.x * 128;
    const int tid = threadIdx.x;
    const int tx = tid & 15;
    const int ty = tid >> 4;

    float acc[8][8];
#pragma unroll
    for (int i = 0; i < 8; i++)
#pragma unroll
        for (int j = 0; j < 8; j++) acc[i][j] = 0.f;

    for (int k0 = 0; k0 < Cz; k0 += 16) {
        if (XLAYOUT) {
            int c  = tid >> 5;
            int mi = (tid & 31) * 4;
#pragma unroll
            for (int p = 0; p < 2; p++, c += 8) {
                int m = m0 + mi;
                int b = m >> 9;
                int t = m & 511;
                float4 v = *(const float4*)&A[(size_t)b * (Cz * Tz) + (size_t)(k0 + c) * Tz + t];
                *(float4*)&As[c][mi] = v;
            }
        } else {
            int c4 = (tid & 3) * 4;
            int mi = tid >> 2;
#pragma unroll
            for (int p = 0; p < 2; p++, mi += 64) {
                float4 v = *(const float4*)&A[(size_t)(m0 + mi) * Cz + k0 + c4];
                As[c4 + 0][mi] = v.x;
                As[c4 + 1][mi] = v.y;
                As[c4 + 2][mi] = v.z;
                As[c4 + 3][mi] = v.w;
            }
        }
        {
            int c  = tid >> 5;
            int g4 = (tid & 31) * 4;
#pragma unroll
            for (int p = 0; p < 2; p++, c += 8) {
                *(float4*)&Bs[c][g4] = *(const float4*)&Wt[(size_t)(k0 + c) * Gz + g0 + g4];
            }
        }
        __syncthreads();

#pragma unroll
        for (int k = 0; k < 16; k++) {
            float a[8], b[8];
            *(float4*)&a[0] = *(float4*)&As[k][ty * 8];
            *(float4*)&a[4] = *(float4*)&As[k][ty * 8 + 4];
            *(float4*)&b[0] = *(float4*)&Bs[k][tx * 8];
            *(float4*)&b[4] = *(float4*)&Bs[k][tx * 8 + 4];
#pragma unroll
            for (int i = 0; i < 8; i++)
#pragma unroll
                for (int j = 0; j < 8; j++)
                    acc[i][j] += a[i] * b[j];
        }
        __syncthreads();
    }

    float bv[8];
#pragma unroll
    for (int j = 0; j < 8; j++) bv[j] = bias[g0 + tx * 8 + j];

#pragma unroll
    for (int i = 0; i < 8; i++) {
        size_t m = (size_t)(m0 + ty * 8 + i);
#pragma unroll
        for (int j = 0; j < 8; j += 4) {
            float4 v;
            v.x = acc[i][j + 0] + bv[j + 0];
            v.y = acc[i][j + 1] + bv[j + 1];
            v.z = acc[i][j + 2] + bv[j + 2];
            v.w = acc[i][j + 3] + bv[j + 3];
            *(float4*)&Cout[m * Gz + g0 + tx * 8 + j] = v;
        }
    }
}

// ---------------- helpers ----------------
__device__ __forceinline__ void cpa16(float* dst_smem, const float* src_gmem)
{
    uint32_t d = (uint32_t)__cvta_generic_to_shared(dst_smem);
    asm volatile("cp.async.cg.shared.global [%0], [%1], 16;" :: "r"(d), "l"(src_gmem));
}
__device__ __forceinline__ void cpa_commit() { asm volatile("cp.async.commit_group;"); }
__device__ __forceinline__ void cpa_wait0()  { asm volatile("cp.async.wait_group 0;" ::: "memory"); }

__device__ __forceinline__ void flag_release(unsigned long long* p, unsigned long long v)
{
    asm volatile("st.release.gpu.global.u64 [%0], %1;" :: "l"(p), "l"(v) : "memory");
}
__device__ __forceinline__ unsigned long long flag_acquire(const unsigned long long* p)
{
    unsigned long long v;
    asm volatile("ld.acquire.gpu.global.u64 %0, [%1];" : "=l"(v) : "l"(p) : "memory");
    return v;
}

__device__ __forceinline__ float sigmoidf_(float x) { return 1.f / (1.f + expf(-x)); }

// ---------------- persistent recurrent kernel ----------------
// 128 blocks x 256 threads. Block b owns h-cols j0..j0+3 => 16 gate-cols.
__global__ void __launch_bounds__(256, 1)
lstm_rec(const float* __restrict__ Whh,
         const float* __restrict__ xp,
         float* __restrict__ outp,
         int layer)
{
    extern __shared__ float sm[];
    float* w_s = sm;              // [512][16]  8192 floats (32 KB)
    float* h_s = sm + 8192;       // [2][64][64] 8192 floats (32 KB)
    float* gs  = sm + 16384;      // [64][17]   1088 floats

    const int tid  = threadIdx.x;
    const int bid  = blockIdx.x;
    const int j0   = bid * 4;
    const int tx   = tid & 15;    // gate column (lc)
    const int ty   = tid >> 4;    // row group: rows 4ty..4ty+3
    const int row2 = tid & 63;    // batch row in phase 2
    const int jj   = tid >> 6;    // h-col (0..3) in phase 2

    const unsigned long long base = g_flag[bid];

    // load W_hh slice: w_s[k][lc] = Whh[gc(lc)][k]
#pragma unroll
    for (int lc = 0; lc < 16; lc++) {
        int gc = (lc >> 2) * Hz + j0 + (lc & 3);
        const float* wr = Whh + (size_t)gc * Hz;
        w_s[tid * 16 + lc]         = wr[tid];
        w_s[(tid + 256) * 16 + lc] = wr[tid + 256];
    }
    // zero my slice of h0; cell state lives in a register
    g_h0[(j0 + jj) * 64 + row2] = 0.f;
    float creg = 0.f;

    // init barrier (gen = base+1)
    __syncthreads();
    if (tid == 0) flag_release(&g_flag[bid], base + 1ULL);
    if (tid < NBLK) {
        while (flag_acquire(&g_flag[tid]) < base + 1ULL) { }
    }
    __syncthreads();

    const float* hprev = g_h0;
    float*       hnext = g_h1;

    for (int t = 0; t < Tz; t++) {
        // prefetch xp for phase 2 (DRAM latency hidden under GEMM)
        float xq0, xq1, xq2, xq3;
        {
            const float* xb = xp + ((size_t)row2 * Tz + t) * Gz + j0 + jj;
            xq0 = __ldg(xb);
            xq1 = __ldg(xb + 1 * Hz);
            xq2 = __ldg(xb + 2 * Hz);
            xq3 = __ldg(xb + 3 * Hz);
        }

        float acc0 = 0.f, acc1 = 0.f, acc2 = 0.f, acc3 = 0.f;

        // preload chunk 0 into buffer 0 via cp.async (L2-fresh)
#pragma unroll
        for (int q = 0; q < 4; q++)
            cpa16(h_s + (tid + q * 256) * 4, hprev + (tid + q * 256) * 4);
        cpa_commit();

        for (int c = 0; c < 8; c++) {
            const int cur = c & 1;
            cpa_wait0();
            __syncthreads();
            if (c < 7) {
                const int nb = cur ^ 1;
                const float* src = hprev + (c + 1) * 4096;
#pragma unroll
                for (int q = 0; q < 4; q++)
                    cpa16(h_s + nb * 4096 + (tid + q * 256) * 4, src + (tid + q * 256) * 4);
                cpa_commit();
            }
            const float* hb = h_s + cur * 4096;
            const float* wb = w_s + (c * 64) * 16;
#pragma unroll
            for (int k = 0; k < 64; k++) {
                float4 hv = *(const float4*)&hb[k * 64 + ty * 4];
                float  wv = wb[k * 16 + tx];
                acc0 += hv.x * wv;
                acc1 += hv.y * wv;
                acc2 += hv.z * wv;
                acc3 += hv.w * wv;
            }
        }

        __syncthreads();
        gs[(ty * 4 + 0) * 17 + tx] = acc0;
        gs[(ty * 4 + 1) * 17 + tx] = acc1;
        gs[(ty * 4 + 2) * 17 + tx] = acc2;
        gs[(ty * 4 + 3) * 17 + tx] = acc3;
        __syncthreads();

        // phase 2: one (row, h-col) per thread
        {
            float gi = gs[row2 * 17 + 0  + jj] + xq0;
            float gf = gs[row2 * 17 + 4  + jj] + xq1;
            float gg = gs[row2 * 17 + 8  + jj] + xq2;
            float go = gs[row2 * 17 + 12 + jj] + xq3;
            float iv = sigmoidf_(gi);
            float fv = sigmoidf_(gf);
            float gv = tanhf(gg);
            float ov = sigmoidf_(go);
            creg = fv * creg + iv * gv;
            float hv = ov * tanhf(creg);
            hnext[(j0 + jj) * 64 + row2] = hv;
            if (layer == 1) {
                g_hseq[((size_t)row2 * Tz + t) * Hz + j0 + jj] = hv;
            } else {
                outp[(size_t)row2 * (Hz * Tz) + (size_t)(j0 + jj) * Tz + t] = hv;
            }
        }

        // grid barrier: release own flag, acquire-poll all flags
        const unsigned long long gen = base + 2ULL + (unsigned long long)t;
        __syncthreads();
        if (tid == 0) flag_release(&g_flag[bid], gen);
        if (tid < NBLK) {
            while (flag_acquire(&g_flag[tid]) < gen) { }
        }
        __syncthreads();

        const float* tmp = hprev;
        hprev = hnext;
        hnext = (float*)tmp;
    }
}

// ---------------- host launcher ----------------
extern "C" void kernel_launch(void* const* d_in, const int* in_sizes, int n_in,
                              void* d_out, int out_size)
{
    const float* x     = (const float*)d_in[0];
    const float* W_ih1 = (const float*)d_in[1];
    const float* W_hh1 = (const float*)d_in[2];
    const float* b_ih1 = (const float*)d_in[3];
    const float* b_hh1 = (const float*)d_in[4];
    const float* W_ih2 = (const float*)d_in[5];
    const float* W_hh2 = (const float*)d_in[6];
    const float* b_ih2 = (const float*)d_in[7];
    const float* b_hh2 = (const float*)d_in[8];
    float* out = (float*)d_out;

    float *p_xp, *p_hseq, *p_wt1, *p_wt2, *p_b1, *p_b2;
    cudaGetSymbolAddress((void**)&p_xp,   g_xp);
    cudaGetSymbolAddress((void**)&p_hseq, g_hseq);
    cudaGetSymbolAddress((void**)&p_wt1,  g_wt1);
    cudaGetSymbolAddress((void**)&p_wt2,  g_wt2);
    cudaGetSymbolAddress((void**)&p_b1,   g_bias1);
    cudaGetSymbolAddress((void**)&p_b2,   g_bias2);

    const int rec_smem = (8192 + 8192 + 64 * 17) * 4;  // 69888 B
    cudaFuncSetAttribute(lstm_rec, cudaFuncAttributeMaxDynamicSharedMemorySize, rec_smem);

    // 1) prep
    lstm_prep<<<(Cz * Gz + 255) / 256, 256>>>(W_ih1, b_ih1, b_hh1, W_ih2, b_ih2, b_hh2);

    // 2) xp1 = x^T-view @ W_ih1^T + (b_ih1 + b_hh1)
    gemm_xp<true><<<dim3(Gz / 128, Mz / 128), 256>>>(x, p_wt1, p_b1, p_xp);

    // 3) recurrence layer 1 -> g_hseq
    lstm_rec<<<NBLK, 256, rec_smem>>>(W_hh1, p_xp, out /*unused*/, 1);

    // 4) xp2 = hseq @ W_ih2^T + (b_ih2 + b_hh2)
    gemm_xp<false><<<dim3(Gz / 128, Mz / 128), 256>>>(p_hseq, p_wt2, p_b2, p_xp);

    // 5) recurrence layer 2 -> out (B, H, T)
    lstm_rec<<<NBLK, 256, rec_smem>>>(W_hh2, p_xp, out, 2);
}

// round 6
// speedup vs baseline: 1.4795x; 1.4795x over previous
#include <cuda_runtime.h>
#include <cuda_fp16.h>
#include <math.h>
#include <stdint.h>

// Problem constants
#define Bz 64
#define Tz 512
#define Cz 512
#define Hz 512
#define Gz 2048    // 4*H
#define Mz (Bz*Tz) // 32768
#define RBLK 64    // recurrent CTAs

// ---------------- device scratch (static, no allocation) ----------------
__device__ float g_xp[(size_t)Mz * Gz];      // [m][g], m = b*T+t
__device__ float g_hseq[(size_t)Mz * Hz];    // [m][c]
__device__ float g_wt1[Cz * Gz];             // W_ih1 transposed [c][g]
__device__ float g_wt2[Hz * Gz];
__device__ float g_bias1[Gz];
__device__ float g_bias2[Gz];
__device__ uint32_t g_wr1[RBLK * 4 * 32 * 64];  // pre-packed B fragments (2MB)
__device__ uint32_t g_wr2[RBLK * 4 * 32 * 64];
__device__ __half g_h[2][Bz * Hz];           // h fp16 double buffer [m][k]
__device__ unsigned long long g_flag[RBLK];  // barrier flags (monotonic)

// ==================== helpers ====================
__device__ __forceinline__ uint32_t smem_u32(const void* p) {
    uint32_t a;
    asm("{ .reg .u64 t; cvta.to.shared.u64 t, %1; cvt.u32.u64 %0, t; }" : "=r"(a) : "l"(p));
    return a;
}
__device__ __forceinline__ void cpa16(uint32_t dst_smem, const void* src) {
    asm volatile("cp.async.cg.shared.global [%0], [%1], 16;" :: "r"(dst_smem), "l"(src));
}
__device__ __forceinline__ void cpa_commit() { asm volatile("cp.async.commit_group;"); }
__device__ __forceinline__ void cpa_wait0()  { asm volatile("cp.async.wait_group 0;" ::: "memory"); }

__device__ __forceinline__ void flag_release(unsigned long long* p, unsigned long long v) {
    asm volatile("st.release.gpu.global.u64 [%0], %1;" :: "l"(p), "l"(v) : "memory");
}
__device__ __forceinline__ unsigned long long flag_acquire(const unsigned long long* p) {
    unsigned long long v;
    asm volatile("ld.acquire.gpu.global.u64 %0, [%1];" : "=l"(v) : "l"(p) : "memory");
    return v;
}

__device__ __forceinline__ void mma16816(float* c,
    uint32_t a0, uint32_t a1, uint32_t a2, uint32_t a3, uint32_t b0, uint32_t b1)
{
    asm volatile(
        "mma.sync.aligned.m16n8k16.row.col.f32.f16.f16.f32 "
        "{%0,%1,%2,%3}, {%4,%5,%6,%7}, {%8,%9}, {%0,%1,%2,%3};"
        : "+f"(c[0]), "+f"(c[1]), "+f"(c[2]), "+f"(c[3])
        : "r"(a0), "r"(a1), "r"(a2), "r"(a3), "r"(b0), "r"(b1));
}

__device__ __forceinline__ float sig_(float x)  { return __fdividef(1.f, 1.f + __expf(-x)); }
__device__ __forceinline__ float tanh_(float x) { return 1.f - 2.f * __fdividef(1.f, __expf(2.f * x) + 1.f); }

// ---------------- prep: transpose W_ih, fold biases ----------------
__global__ void lstm_prep(const float* __restrict__ Wih1,
                          const float* __restrict__ bih1,
                          const float* __restrict__ bhh1,
                          const float* __restrict__ Wih2,
                          const float* __restrict__ bih2,
                          const float* __restrict__ bhh2)
{
    int i = blockIdx.x * blockDim.x + threadIdx.x;
    if (i < Cz * Gz) {
        int g = i / Cz;
        int c = i - g * Cz;
        g_wt1[(size_t)c * Gz + g] = Wih1[(size_t)g * Cz + c];
        g_wt2[(size_t)c * Gz + g] = Wih2[(size_t)g * Cz + c];
    }
    if (i < Gz) {
        g_bias1[i] = bih1[i] + bhh1[i];
        g_bias2[i] = bih2[i] + bhh2[i];
    }
}

// ---------------- prep: pack W_hh into mma.sync B fragments ----------------
// B[k][nc] = W_hh[gate*512 + n*8 + col][k], nc = gate*8 + col.
// m16n8k16 B frag, lane l, k-step ks (k0=16*ks):
//   reg0 = {B[k0+(l%4)*2][l/4], B[k0+(l%4)*2+1][l/4]}
//   reg1 = {B[k0+(l%4)*2+8][l/4], B[k0+(l%4)*2+9][l/4]}
// layout: [n][w][lane][ks*2 + r]  (each lane's 64 u32 contiguous)
__global__ void prep_wr(const float* __restrict__ Whh1, const float* __restrict__ Whh2)
{
    int e = blockIdx.x * blockDim.x + threadIdx.x;   // [l][n][w][lane][ks]
    if (e >= 2 * RBLK * 4 * 32 * 32) return;
    int ks   = e & 31;
    int lane = (e >> 5) & 31;
    int w    = (e >> 10) & 3;
    int n    = (e >> 12) & 63;
    int l    = e >> 18;
    const float* W = l ? Whh2 : Whh1;
    int wrow = w * Hz + n * 8 + (lane >> 2);
    int kb   = ks * 16 + (lane & 3) * 2;
    const float* r = W + (size_t)wrow * Hz;
    __half2 v0 = __floats2half2_rn(r[kb],     r[kb + 1]);
    __half2 v1 = __floats2half2_rn(r[kb + 8], r[kb + 9]);
    uint32_t* dst = l ? g_wr2 : g_wr1;
    size_t idx = ((((size_t)n * 4 + w) * 32 + lane) * 32 + ks) * 2;
    dst[idx]     = *(const uint32_t*)&v0;
    dst[idx + 1] = *(const uint32_t*)&v1;
}

// ---------------- xp GEMM (unchanged) ----------------
template<bool XLAYOUT>
__global__ void __launch_bounds__(256)
gemm_xp(const float* __restrict__ A,
        const float* __restrict__ Wt,
        const float* __restrict__ bias,
        float* __restrict__ Cout)
{
    __shared__ float As[16][128];
    __shared__ float Bs[16][128];

    const int m0 = blockIdx.y * 128;
    const int g0 = blockIdx.x * 128;
    const int tid = threadIdx.x;
    const int tx = tid & 15;
    const int ty = tid >> 4;

    float acc[8][8];
#pragma unroll
    for (int i = 0; i < 8; i++)
#pragma unroll
        for (int j = 0; j < 8; j++) acc[i][j] = 0.f;

    for (int k0 = 0; k0 < Cz; k0 += 16) {
        if (XLAYOUT) {
            int c  = tid >> 5;
            int mi = (tid & 31) * 4;
#pragma unroll
            for (int p = 0; p < 2; p++, c += 8) {
                int m = m0 + mi;
                int b = m >> 9;
                int t = m & 511;
                float4 v = *(const float4*)&A[(size_t)b * (Cz * Tz) + (size_t)(k0 + c) * Tz + t];
                *(float4*)&As[c][mi] = v;
            }
        } else {
            int c4 = (tid & 3) * 4;
            int mi = tid >> 2;
#pragma unroll
            for (int p = 0; p < 2; p++, mi += 64) {
                float4 v = *(const float4*)&A[(size_t)(m0 + mi) * Cz + k0 + c4];
                As[c4 + 0][mi] = v.x;
                As[c4 + 1][mi] = v.y;
                As[c4 + 2][mi] = v.z;
                As[c4 + 3][mi] = v.w;
            }
        }
        {
            int c  = tid >> 5;
            int g4 = (tid & 31) * 4;
#pragma unroll
            for (int p = 0; p < 2; p++, c += 8) {
                *(float4*)&Bs[c][g4] = *(const float4*)&Wt[(size_t)(k0 + c) * Gz + g0 + g4];
            }
        }
        __syncthreads();

#pragma unroll
        for (int k = 0; k < 16; k++) {
            float a[8], b[8];
            *(float4*)&a[0] = *(float4*)&As[k][ty * 8];
            *(float4*)&a[4] = *(float4*)&As[k][ty * 8 + 4];
            *(float4*)&b[0] = *(float4*)&Bs[k][tx * 8];
            *(float4*)&b[4] = *(float4*)&Bs[k][tx * 8 + 4];
#pragma unroll
            for (int i = 0; i < 8; i++)
#pragma unroll
                for (int j = 0; j < 8; j++)
                    acc[i][j] += a[i] * b[j];
        }
        __syncthreads();
    }

    float bv[8];
#pragma unroll
    for (int j = 0; j < 8; j++) bv[j] = bias[g0 + tx * 8 + j];

#pragma unroll
    for (int i = 0; i < 8; i++) {
        size_t m = (size_t)(m0 + ty * 8 + i);
#pragma unroll
        for (int j = 0; j < 8; j += 4) {
            float4 v;
            v.x = acc[i][j + 0] + bv[j + 0];
            v.y = acc[i][j + 1] + bv[j + 1];
            v.z = acc[i][j + 2] + bv[j + 2];
            v.w = acc[i][j + 3] + bv[j + 3];
            *(float4*)&Cout[m * Gz + g0 + tx * 8 + j] = v;
        }
    }
}

// ---------------- persistent mma.sync recurrent kernel ----------------
// 64 CTAs x 128 threads (4 warps). CTA n owns h-cols [8n, 8n+8); warp w = gate w.
// Per step: gates[64 x 32] = h[64 x 512] @ W'^T via m16n8k16 HMMA,
// W' B-fragments register-resident for the whole layer.
// SMEM: h_s 64 rows x 520 halves (66560 B), gs 64x33 f32 (8448 B).
#define HSTRIDE 520
__global__ void __launch_bounds__(128, 1)
lstm_rec(const uint32_t* __restrict__ wr,
         const float* __restrict__ xp,
         float* __restrict__ outp,
         int layer)
{
    extern __shared__ __align__(16) char sm[];
    __half* h_s = (__half*)sm;                   // [64][520]
    float*  gs  = (float*)(sm + 66560);          // [64][33]
    const uint32_t hs_base = smem_u32(h_s);

    const int tid  = threadIdx.x;
    const int w    = tid >> 5;
    const int lane = tid & 31;
    const int n    = blockIdx.x;

    // ---- load register-resident B fragments (64 u32/lane) ----
    uint32_t wB[64];
    {
        const uint4* p = (const uint4*)(wr + (((size_t)n * 4 + w) * 32 + lane) * 64);
#pragma unroll
        for (int q = 0; q < 16; q++) {
            uint4 v = p[q];
            wB[q * 4 + 0] = v.x; wB[q * 4 + 1] = v.y;
            wB[q * 4 + 2] = v.z; wB[q * 4 + 3] = v.w;
        }
    }

    // epilogue mapping: thread -> (batch row em, col-half jh)
    const int em = tid & 63;
    const int jh = tid >> 6;
    float creg[4] = {0.f, 0.f, 0.f, 0.f};

    // zero my slice of h0
    {
        uint2 zz = make_uint2(0, 0);
        *(uint2*)((char*)&g_h[0][0] + (size_t)(em * Hz + n * 8 + jh * 4) * 2) = zz;
    }

    const unsigned long long base = g_flag[n];
    __threadfence();
    __syncthreads();
    if (tid == 0) flag_release(&g_flag[n], base + 1ULL);
    if (tid < RBLK) { while (flag_acquire(&g_flag[tid]) < base + 1ULL) { } }
    __syncthreads();

    // A-fragment smem base for this lane (row = lane/4, col byte = (lane%4)*4)
    const uint32_t a_base = hs_base + (uint32_t)((lane >> 2) * HSTRIDE * 2 + (lane & 3) * 4);
    const int crow = lane >> 2;
    const int ccol = w * 8 + (lane & 3) * 2;

    for (int t = 0; t < Tz; t++) {
        // ---- cp.async h into SMEM (padded rows) ----
        {
            const char* hsrc = (const char*)&g_h[t & 1][0];
#pragma unroll
            for (int q = 0; q < 32; q++) {
                int z = q * 128 + tid;
                int row = z >> 6, cc = z & 63;
                cpa16(hs_base + row * (HSTRIDE * 2) + cc * 16, hsrc + z * 16);
            }
            cpa_commit();
        }

        // ---- xp prefetch (independent) ----
        float4 xq[4];
        {
            const float* xb = xp + ((size_t)em * Tz + t) * Gz + n * 8 + jh * 4;
#pragma unroll
            for (int g = 0; g < 4; g++)
                xq[g] = __ldg((const float4*)(xb + g * Hz));
        }

        cpa_wait0();
        __syncthreads();

        // ---- MMA: 4 M-tiles x 32 k-steps ----
        float c_[4][4];
#pragma unroll
        for (int mt = 0; mt < 4; mt++)
#pragma unroll
            for (int i = 0; i < 4; i++) c_[mt][i] = 0.f;

#pragma unroll
        for (int ks = 0; ks < 32; ks++) {
            const uint32_t cb = a_base + ks * 32;   // +16 halves = 32 B per k-step
#pragma unroll
            for (int mt = 0; mt < 4; mt++) {
                const uint32_t pa = cb + mt * (16 * HSTRIDE * 2);
                uint32_t a0, a1, a2, a3;
                asm volatile("ld.shared.b32 %0, [%1];" : "=r"(a0) : "r"(pa));
                asm volatile("ld.shared.b32 %0, [%1];" : "=r"(a1) : "r"(pa + 8 * HSTRIDE * 2));
                asm volatile("ld.shared.b32 %0, [%1];" : "=r"(a2) : "r"(pa + 16));
                asm volatile("ld.shared.b32 %0, [%1];" : "=r"(a3) : "r"(pa + 8 * HSTRIDE * 2 + 16));
                mma16816(c_[mt], a0, a1, a2, a3, wB[ks * 2], wB[ks * 2 + 1]);
            }
        }

        // ---- stage gates in SMEM ----
        __syncthreads();   // everyone done reading h_s (gs separate, but cheap safety)
#pragma unroll
        for (int mt = 0; mt < 4; mt++) {
            gs[(mt * 16 + crow) * 33 + ccol]         = c_[mt][0];
            gs[(mt * 16 + crow) * 33 + ccol + 1]     = c_[mt][1];
            gs[(mt * 16 + crow + 8) * 33 + ccol]     = c_[mt][2];
            gs[(mt * 16 + crow + 8) * 33 + ccol + 1] = c_[mt][3];
        }
        __syncthreads();

        // ---- epilogue: 4 outputs per thread ----
        float hv[4];
#pragma unroll
        for (int s = 0; s < 4; s++) {
            int jl = jh * 4 + s;
            float gi = gs[em * 33 + jl]      + ((const float*)&xq[0])[s];
            float gf = gs[em * 33 + 8 + jl]  + ((const float*)&xq[1])[s];
            float gg = gs[em * 33 + 16 + jl] + ((const float*)&xq[2])[s];
            float go = gs[em * 33 + 24 + jl] + ((const float*)&xq[3])[s];
            float iv = sig_(gi);
            float fv = sig_(gf);
            float gv = tanh_(gg);
            float ov = sig_(go);
            creg[s] = fv * creg[s] + iv * gv;
            hv[s] = ov * tanh_(creg[s]);
        }
        // fp16 h -> next buffer
        {
            __half2 p0 = __floats2half2_rn(hv[0], hv[1]);
            __half2 p1 = __floats2half2_rn(hv[2], hv[3]);
            uint2 pk;
            pk.x = *(const uint32_t*)&p0;
            pk.y = *(const uint32_t*)&p1;
            *(uint2*)((char*)&g_h[(t + 1) & 1][0] + (size_t)(em * Hz + n * 8 + jh * 4) * 2) = pk;
        }
        // layer output fp32
        if (layer == 1) {
            float4 v = make_float4(hv[0], hv[1], hv[2], hv[3]);
            *(float4*)&g_hseq[((size_t)em * Tz + t) * Hz + n * 8 + jh * 4] = v;
        } else {
#pragma unroll
            for (int s = 0; s < 4; s++)
                outp[(size_t)em * (Hz * Tz) + (size_t)(n * 8 + jh * 4 + s) * Tz + t] = hv[s];
        }

        // ---- grid barrier ----
        __threadfence();
        __syncthreads();
        const unsigned long long gen = base + 2ULL + (unsigned long long)t;
        if (tid == 0) flag_release(&g_flag[n], gen);
        if (tid < RBLK) { while (flag_acquire(&g_flag[tid]) < gen) { } }
        __syncthreads();
    }
}

// ---------------- host launcher ----------------
extern "C" void kernel_launch(void* const* d_in, const int* in_sizes, int n_in,
                              void* d_out, int out_size)
{
    const float* x     = (const float*)d_in[0];
    const float* W_ih1 = (const float*)d_in[1];
    const float* W_hh1 = (const float*)d_in[2];
    const float* b_ih1 = (const float*)d_in[3];
    const float* b_hh1 = (const float*)d_in[4];
    const float* W_ih2 = (const float*)d_in[5];
    const float* W_hh2 = (const float*)d_in[6];
    const float* b_ih2 = (const float*)d_in[7];
    const float* b_hh2 = (const float*)d_in[8];
    float* out = (float*)d_out;

    float *p_xp, *p_hseq, *p_wt1, *p_wt2, *p_b1, *p_b2;
    uint32_t *p_wr1, *p_wr2;
    cudaGetSymbolAddress((void**)&p_xp,   g_xp);
    cudaGetSymbolAddress((void**)&p_hseq, g_hseq);
    cudaGetSymbolAddress((void**)&p_wt1,  g_wt1);
    cudaGetSymbolAddress((void**)&p_wt2,  g_wt2);
    cudaGetSymbolAddress((void**)&p_b1,   g_bias1);
    cudaGetSymbolAddress((void**)&p_b2,   g_bias2);
    cudaGetSymbolAddress((void**)&p_wr1,  g_wr1);
    cudaGetSymbolAddress((void**)&p_wr2,  g_wr2);

    const int rec_smem = 66560 + 64 * 33 * 4;  // 75008 B
    cudaFuncSetAttribute(lstm_rec, cudaFuncAttributeMaxDynamicSharedMemorySize, rec_smem);

    // prep
    lstm_prep<<<(Cz * Gz + 255) / 256, 256>>>(W_ih1, b_ih1, b_hh1, W_ih2, b_ih2, b_hh2);
    prep_wr<<<(2 * RBLK * 4 * 32 * 32 + 255) / 256, 256>>>(W_hh1, W_hh2);

    // xp1 = x^T-view @ W_ih1^T + bias1
    gemm_xp<true><<<dim3(Gz / 128, Mz / 128), 256>>>(x, p_wt1, p_b1, p_xp);

    // recurrence layer 1 -> g_hseq
    lstm_rec<<<RBLK, 128, rec_smem>>>(p_wr1, p_xp, out /*unused*/, 1);

    // xp2 = hseq @ W_ih2^T + bias2
    gemm_xp<false><<<dim3(Gz / 128, Mz / 128), 256>>>(p_hseq, p_wt2, p_b2, p_xp);

    // recurrence layer 2 -> out (B, H, T)
    lstm_rec<<<RBLK, 128, rec_smem>>>(p_wr2, p_xp, out, 2);
}

// round 7
// speedup vs baseline: 1.5797x; 1.0677x over previous
#include <cuda_runtime.h>
#include <cuda_fp16.h>
#include <math.h>
#include <stdint.h>

// Problem constants
#define Bz 64
#define Tz 512
#define Cz 512
#define Hz 512
#define Gz 2048    // 4*H
#define Mz (Bz*Tz) // 32768
#define RBLK 32    // recurrent CTAs

// ---------------- device scratch (static, no allocation) ----------------
__device__ float g_xp[(size_t)Mz * Gz];      // [m][g], m = b*T+t
__device__ float g_hseq[(size_t)Mz * Hz];    // [m][c]
__device__ float g_wt1[Cz * Gz];             // W_ih1 transposed [c][g]
__device__ float g_wt2[Hz * Gz];
__device__ float g_bias1[Gz];
__device__ float g_bias2[Gz];
__device__ uint32_t g_wr1[RBLK * 8 * 32 * 64];  // pre-packed B fragments (2MB)
__device__ uint32_t g_wr2[RBLK * 8 * 32 * 64];
__device__ __half g_h[2][Bz * Hz];           // h fp16 double buffer [m][k]
__device__ unsigned long long g_flag[RBLK];  // barrier flags (monotonic)

// ==================== helpers ====================
__device__ __forceinline__ uint32_t smem_u32(const void* p) {
    uint32_t a;
    asm("{ .reg .u64 t; cvta.to.shared.u64 t, %1; cvt.u32.u64 %0, t; }" : "=r"(a) : "l"(p));
    return a;
}
__device__ __forceinline__ void cpa16(uint32_t dst_smem, const void* src) {
    asm volatile("cp.async.cg.shared.global [%0], [%1], 16;" :: "r"(dst_smem), "l"(src));
}
__device__ __forceinline__ void cpa_commit() { asm volatile("cp.async.commit_group;"); }
__device__ __forceinline__ void cpa_wait0()  { asm volatile("cp.async.wait_group 0;" ::: "memory"); }

__device__ __forceinline__ void flag_release(unsigned long long* p, unsigned long long v) {
    asm volatile("st.release.gpu.global.u64 [%0], %1;" :: "l"(p), "l"(v) : "memory");
}
__device__ __forceinline__ unsigned long long flag_acquire(const unsigned long long* p) {
    unsigned long long v;
    asm volatile("ld.acquire.gpu.global.u64 %0, [%1];" : "=l"(v) : "l"(p) : "memory");
    return v;
}

__device__ __forceinline__ void mma16816(float* c,
    uint32_t a0, uint32_t a1, uint32_t a2, uint32_t a3, uint32_t b0, uint32_t b1)
{
    asm volatile(
        "mma.sync.aligned.m16n8k16.row.col.f32.f16.f16.f32 "
        "{%0,%1,%2,%3}, {%4,%5,%6,%7}, {%8,%9}, {%0,%1,%2,%3};"
        : "+f"(c[0]), "+f"(c[1]), "+f"(c[2]), "+f"(c[3])
        : "r"(a0), "r"(a1), "r"(a2), "r"(a3), "r"(b0), "r"(b1));
}

__device__ __forceinline__ void ldsm4(uint32_t& a0, uint32_t& a1, uint32_t& a2, uint32_t& a3,
                                      uint32_t addr)
{
    asm volatile("ldmatrix.sync.aligned.m8n8.x4.shared.b16 {%0,%1,%2,%3}, [%4];"
                 : "=r"(a0), "=r"(a1), "=r"(a2), "=r"(a3) : "r"(addr));
}

__device__ __forceinline__ float sig_(float x)  { return __fdividef(1.f, 1.f + __expf(-x)); }
__device__ __forceinline__ float tanh_(float x) { return 1.f - 2.f * __fdividef(1.f, __expf(2.f * x) + 1.f); }

// ---------------- prep: transpose W_ih, fold biases ----------------
__global__ void lstm_prep(const float* __restrict__ Wih1,
                          const float* __restrict__ bih1,
                          const float* __restrict__ bhh1,
                          const float* __restrict__ Wih2,
                          const float* __restrict__ bih2,
                          const float* __restrict__ bhh2)
{
    int i = blockIdx.x * blockDim.x + threadIdx.x;
    if (i < Cz * Gz) {
        int g = i / Cz;
        int c = i - g * Cz;
        g_wt1[(size_t)c * Gz + g] = Wih1[(size_t)g * Cz + c];
        g_wt2[(size_t)c * Gz + g] = Wih2[(size_t)g * Cz + c];
    }
    if (i < Gz) {
        g_bias1[i] = bih1[i] + bhh1[i];
        g_bias2[i] = bih2[i] + bhh2[i];
    }
}

// ---------------- prep: pack W_hh into mma.sync B fragments ----------------
// CTA n owns h-cols [16n,16n+16). Warp w (0..7): gate = w>>1, col block = (w&1)*8.
// W row for (w, ncol) = gate*512 + 16n + (w&1)*8 + ncol, ncol = lane>>2.
// frag reg0 = {B[ks16+(l&3)*2], +1}, reg1 = {+8, +9} along k.
__global__ void prep_wr(const float* __restrict__ Whh1, const float* __restrict__ Whh2)
{
    int e = blockIdx.x * blockDim.x + threadIdx.x;   // [l][n][w][lane][ks]
    if (e >= 2 * RBLK * 8 * 32 * 32) return;
    int ks   = e & 31;
    int lane = (e >> 5) & 31;
    int w    = (e >> 10) & 7;
    int n    = (e >> 13) & 31;
    int l    = e >> 18;
    const float* W = l ? Whh2 : Whh1;
    int wrow = (w >> 1) * Hz + n * 16 + (w & 1) * 8 + (lane >> 2);
    int kb   = ks * 16 + (lane & 3) * 2;
    const float* r = W + (size_t)wrow * Hz;
    __half2 v0 = __floats2half2_rn(r[kb],     r[kb + 1]);
    __half2 v1 = __floats2half2_rn(r[kb + 8], r[kb + 9]);
    uint32_t* dst = l ? g_wr2 : g_wr1;
    size_t idx = ((((size_t)n * 8 + w) * 32 + lane) * 32 + ks) * 2;
    dst[idx]     = *(const uint32_t*)&v0;
    dst[idx + 1] = *(const uint32_t*)&v1;
}

// ---------------- xp GEMM (unchanged) ----------------
template<bool XLAYOUT>
__global__ void __launch_bounds__(256)
gemm_xp(const float* __restrict__ A,
        const float* __restrict__ Wt,
        const float* __restrict__ bias,
        float* __restrict__ Cout)
{
    __shared__ float As[16][128];
    __shared__ float Bs[16][128];

    const int m0 = blockIdx.y * 128;
    const int g0 = blockIdx.x * 128;
    const int tid = threadIdx.x;
    const int tx = tid & 15;
    const int ty = tid >> 4;

    float acc[8][8];
#pragma unroll
    for (int i = 0; i < 8; i++)
#pragma unroll
        for (int j = 0; j < 8; j++) acc[i][j] = 0.f;

    for (int k0 = 0; k0 < Cz; k0 += 16) {
        if (XLAYOUT) {
            int c  = tid >> 5;
            int mi = (tid & 31) * 4;
#pragma unroll
            for (int p = 0; p < 2; p++, c += 8) {
                int m = m0 + mi;
                int b = m >> 9;
                int t = m & 511;
                float4 v = *(const float4*)&A[(size_t)b * (Cz * Tz) + (size_t)(k0 + c) * Tz + t];
                *(float4*)&As[c][mi] = v;
            }
        } else {
            int c4 = (tid & 3) * 4;
            int mi = tid >> 2;
#pragma unroll
            for (int p = 0; p < 2; p++, mi += 64) {
                float4 v = *(const float4*)&A[(size_t)(m0 + mi) * Cz + k0 + c4];
                As[c4 + 0][mi] = v.x;
                As[c4 + 1][mi] = v.y;
                As[c4 + 2][mi] = v.z;
                As[c4 + 3][mi] = v.w;
            }
        }
        {
            int c  = tid >> 5;
            int g4 = (tid & 31) * 4;
#pragma unroll
            for (int p = 0; p < 2; p++, c += 8) {
                *(float4*)&Bs[c][g4] = *(const float4*)&Wt[(size_t)(k0 + c) * Gz + g0 + g4];
            }
        }
        __syncthreads();

#pragma unroll
        for (int k = 0; k < 16; k++) {
            float a[8], b[8];
            *(float4*)&a[0] = *(float4*)&As[k][ty * 8];
            *(float4*)&a[4] = *(float4*)&As[k][ty * 8 + 4];
            *(float4*)&b[0] = *(float4*)&Bs[k][tx * 8];
            *(float4*)&b[4] = *(float4*)&Bs[k][tx * 8 + 4];
#pragma unroll
            for (int i = 0; i < 8; i++)
#pragma unroll
                for (int j = 0; j < 8; j++)
                    acc[i][j] += a[i] * b[j];
        }
        __syncthreads();
    }

    float bv[8];
#pragma unroll
    for (int j = 0; j < 8; j++) bv[j] = bias[g0 + tx * 8 + j];

#pragma unroll
    for (int i = 0; i < 8; i++) {
        size_t m = (size_t)(m0 + ty * 8 + i);
#pragma unroll
        for (int j = 0; j < 8; j += 4) {
            float4 v;
            v.x = acc[i][j + 0] + bv[j + 0];
            v.y = acc[i][j + 1] + bv[j + 1];
            v.z = acc[i][j + 2] + bv[j + 2];
            v.w = acc[i][j + 3] + bv[j + 3];
            *(float4*)&Cout[m * Gz + g0 + tx * 8 + j] = v;
        }
    }
}

// ---------------- persistent mma.sync recurrent kernel ----------------
// 32 CTAs x 256 threads (8 warps). CTA n owns h-cols [16n, 16n+16);
// warp w: gate w>>1, col block (w&1)*8. W' B-fragments register-resident.
// h output stored coalesced [m][c] into hout; transpose happens at the end.
#define HSTRIDE 520
__global__ void __launch_bounds__(256, 1)
lstm_rec(const uint32_t* __restrict__ wr,
         const float* __restrict__ xp,
         float* __restrict__ hout)
{
    extern __shared__ __align__(16) char sm[];
    __half* h_s = (__half*)sm;                   // [64][520]  66560 B
    float*  gs  = (float*)(sm + 66560);          // [64][65]   16640 B
    const uint32_t hs_base = smem_u32(h_s);

    const int tid  = threadIdx.x;
    const int w    = tid >> 5;
    const int lane = tid & 31;
    const int n    = blockIdx.x;

    // ---- register-resident B fragments (64 u32/lane) ----
    uint32_t wB[64];
    {
        const uint4* p = (const uint4*)(wr + (((size_t)n * 8 + w) * 32 + lane) * 64);
#pragma unroll
        for (int q = 0; q < 16; q++) {
            uint4 v = p[q];
            wB[q * 4 + 0] = v.x; wB[q * 4 + 1] = v.y;
            wB[q * 4 + 2] = v.z; wB[q * 4 + 3] = v.w;
        }
    }

    // epilogue mapping: em = tid>>2 (batch row), quad = tid&3 (4 h-cols each)
    const int em   = tid >> 2;
    const int quad = tid & 3;
    float creg[4] = {0.f, 0.f, 0.f, 0.f};

    // zero my slice of h0
    {
        uint2 zz = make_uint2(0, 0);
        *(uint2*)((char*)&g_h[0][0] + (size_t)(em * Hz + n * 16 + quad * 4) * 2) = zz;
    }

    const unsigned long long base = g_flag[n];
    __threadfence();
    __syncthreads();
    if (tid == 0) flag_release(&g_flag[n], base + 1ULL);
    if (tid < RBLK) { while (flag_acquire(&g_flag[tid]) < base + 1ULL) { } }
    __syncthreads();

    // ldmatrix source address (canonical x4 A-fragment addressing)
    const uint32_t a_base = hs_base +
        (uint32_t)(((lane & 15) * HSTRIDE + (lane >> 4) * 8) * 2);
    // gs staging indices
    const int crow = lane >> 2;
    const int sc   = (w >> 1) * 16 + (w & 1) * 8 + (lane & 3) * 2;

    for (int t = 0; t < Tz; t++) {
        // ---- cp.async h(t) into SMEM (padded rows) ----
        {
            const char* hsrc = (const char*)&g_h[t & 1][0];
#pragma unroll
            for (int q = 0; q < 16; q++) {
                int z = q * 256 + tid;
                int row = z >> 6, cc = z & 63;
                cpa16(hs_base + row * (HSTRIDE * 2) + cc * 16, hsrc + z * 16);
            }
            cpa_commit();
        }

        // ---- xp prefetch (independent) ----
        float4 xq[4];
        {
            const float* xb = xp + ((size_t)em * Tz + t) * Gz + n * 16 + quad * 4;
#pragma unroll
            for (int g = 0; g < 4; g++)
                xq[g] = __ldg((const float4*)(xb + g * Hz));
        }

        cpa_wait0();
        __syncthreads();

        // ---- MMA: 4 M-tiles x 32 k-steps, ldmatrix.x4 A frags ----
        float c_[4][4];
#pragma unroll
        for (int mt = 0; mt < 4; mt++)
#pragma unroll
            for (int i = 0; i < 4; i++) c_[mt][i] = 0.f;

#pragma unroll
        for (int ks = 0; ks < 32; ks++) {
#pragma unroll
            for (int mt = 0; mt < 4; mt++) {
                uint32_t a0, a1, a2, a3;
                ldsm4(a0, a1, a2, a3,
                      a_base + (uint32_t)(mt * (16 * HSTRIDE * 2) + ks * 32));
                mma16816(c_[mt], a0, a1, a2, a3, wB[ks * 2], wB[ks * 2 + 1]);
            }
        }

        // ---- stage gates in SMEM ----
#pragma unroll
        for (int mt = 0; mt < 4; mt++) {
            gs[(mt * 16 + crow) * 65 + sc]         = c_[mt][0];
            gs[(mt * 16 + crow) * 65 + sc + 1]     = c_[mt][1];
            gs[(mt * 16 + crow + 8) * 65 + sc]     = c_[mt][2];
            gs[(mt * 16 + crow + 8) * 65 + sc + 1] = c_[mt][3];
        }
        __syncthreads();

        // ---- epilogue: 4 outputs per thread ----
        float hv[4];
#pragma unroll
        for (int s = 0; s < 4; s++) {
            int jl = quad * 4 + s;
            float gi = gs[em * 65 + jl]      + ((const float*)&xq[0])[s];
            float gf = gs[em * 65 + 16 + jl] + ((const float*)&xq[1])[s];
            float gg = gs[em * 65 + 32 + jl] + ((const float*)&xq[2])[s];
            float go = gs[em * 65 + 48 + jl] + ((const float*)&xq[3])[s];
            float iv = sig_(gi);
            float fv = sig_(gf);
            float gv = tanh_(gg);
            float ov = sig_(go);
            creg[s] = fv * creg[s] + iv * gv;
            hv[s] = ov * tanh_(creg[s]);
        }
        // fp16 h -> next buffer (8B coalesced)
        {
            __half2 p0 = __floats2half2_rn(hv[0], hv[1]);
            __half2 p1 = __floats2half2_rn(hv[2], hv[3]);
            uint2 pk;
            pk.x = *(const uint32_t*)&p0;
            pk.y = *(const uint32_t*)&p1;
            *(uint2*)((char*)&g_h[(t + 1) & 1][0] + (size_t)(em * Hz + n * 16 + quad * 4) * 2) = pk;
        }
        // fp32 h -> [m][c] (coalesced float4)
        {
            float4 v = make_float4(hv[0], hv[1], hv[2], hv[3]);
            *(float4*)&hout[((size_t)em * Tz + t) * Hz + n * 16 + quad * 4] = v;
        }

        // ---- grid barrier (release/acquire; no MEMBAR) ----
        __syncthreads();
        const unsigned long long gen = base + 2ULL + (unsigned long long)t;
        if (tid == 0) flag_release(&g_flag[n], gen);
        if (tid < RBLK) { while (flag_acquire(&g_flag[tid]) < gen) { } }
        __syncthreads();
    }
}

// ---------------- final transpose: hseq [b][t][c] -> out [b][c][t] ----------
__global__ void __launch_bounds__(256)
transpose_out(const float* __restrict__ hseq, float* __restrict__ out)
{
    __shared__ float smt[32][33];
    const int t0 = blockIdx.x * 32;
    const int c0 = blockIdx.y * 32;
    const int b  = blockIdx.z;
    const int tx = threadIdx.x;
    const int ty = threadIdx.y;

#pragma unroll
    for (int i = 0; i < 4; i++)
        smt[ty + i * 8][tx] = hseq[((size_t)b * Tz + t0 + ty + i * 8) * Hz + c0 + tx];
    __syncthreads();
#pragma unroll
    for (int i = 0; i < 4; i++)
        out[(size_t)b * (Hz * Tz) + (size_t)(c0 + ty + i * 8) * Tz + t0 + tx] = smt[tx][ty + i * 8];
}

// ---------------- host launcher ----------------
extern "C" void kernel_launch(void* const* d_in, const int* in_sizes, int n_in,
                              void* d_out, int out_size)
{
    const float* x     = (const float*)d_in[0];
    const float* W_ih1 = (const float*)d_in[1];
    const float* W_hh1 = (const float*)d_in[2];
    const float* b_ih1 = (const float*)d_in[3];
    const float* b_hh1 = (const float*)d_in[4];
    const float* W_ih2 = (const float*)d_in[5];
    const float* W_hh2 = (const float*)d_in[6];
    const float* b_ih2 = (const float*)d_in[7];
    const float* b_hh2 = (const float*)d_in[8];
    float* out = (float*)d_out;

    float *p_xp, *p_hseq, *p_wt1, *p_wt2, *p_b1, *p_b2;
    uint32_t *p_wr1, *p_wr2;
    cudaGetSymbolAddress((void**)&p_xp,   g_xp);
    cudaGetSymbolAddress((void**)&p_hseq, g_hseq);
    cudaGetSymbolAddress((void**)&p_wt1,  g_wt1);
    cudaGetSymbolAddress((void**)&p_wt2,  g_wt2);
    cudaGetSymbolAddress((void**)&p_b1,   g_bias1);
    cudaGetSymbolAddress((void**)&p_b2,   g_bias2);
    cudaGetSymbolAddress((void**)&p_wr1,  g_wr1);
    cudaGetSymbolAddress((void**)&p_wr2,  g_wr2);

    const int rec_smem = 66560 + 64 * 65 * 4;  // 83200 B
    cudaFuncSetAttribute(lstm_rec, cudaFuncAttributeMaxDynamicSharedMemorySize, rec_smem);

    // prep
    lstm_prep<<<(Cz * Gz + 255) / 256, 256>>>(W_ih1, b_ih1, b_hh1, W_ih2, b_ih2, b_hh2);
    prep_wr<<<(2 * RBLK * 8 * 32 * 32 + 255) / 256, 256>>>(W_hh1, W_hh2);

    // xp1 = x^T-view @ W_ih1^T + bias1
    gemm_xp<true><<<dim3(Gz / 128, Mz / 128), 256>>>(x, p_wt1, p_b1, p_xp);

    // recurrence layer 1 -> g_hseq [m][c]
    lstm_rec<<<RBLK, 256, rec_smem>>>(p_wr1, p_xp, p_hseq);

    // xp2 = hseq @ W_ih2^T + bias2
    gemm_xp<false><<<dim3(Gz / 128, Mz / 128), 256>>>(p_hseq, p_wt2, p_b2, p_xp);

    // recurrence layer 2 -> g_hseq [m][c] (overwrites; xp2 already extracted)
    lstm_rec<<<RBLK, 256, rec_smem>>>(p_wr2, p_xp, p_hseq);

    // final transpose -> out (B, H, T)
    transpose_out<<<dim3(Tz / 32, Hz / 32, Bz), dim3(32, 8)>>>(p_hseq, out);
}

// round 8
// speedup vs baseline: 2.8498x; 1.8040x over previous
#include <cuda_runtime.h>
#include <cuda_fp16.h>
#include <math.h>
#include <stdint.h>

// Problem constants
#define Bz 64
#define Tz 512
#define Cz 512
#define Hz 512
#define Gz 2048    // 4*H
#define Mz (Bz*Tz) // 32768
#define NSLICE 32  // h-col slices (CTAs per group)
#define NGRP 4     // batch groups (16 rows each)

// ---------------- device scratch (static, no allocation) ----------------
__device__ float g_xp[(size_t)Mz * Gz];      // [m][g], m = b*T+t
__device__ float g_hseq[(size_t)Mz * Hz];    // [m][c]
__device__ float g_wt1[Cz * Gz];             // W_ih1 transposed [c][g]
__device__ float g_wt2[Hz * Gz];
__device__ float g_bias1[Gz];
__device__ float g_bias2[Gz];
__device__ uint32_t g_wr1[NSLICE * 8 * 32 * 64];  // pre-packed B fragments (2MB)
__device__ uint32_t g_wr2[NSLICE * 8 * 32 * 64];
__device__ __half g_h[NGRP][2][16 * Hz];     // per-group h fp16 double buffer
__device__ unsigned long long g_flag[NGRP][NSLICE][16];  // padded flags (128B each)

// ==================== helpers ====================
__device__ __forceinline__ uint32_t smem_u32(const void* p) {
    uint32_t a;
    asm("{ .reg .u64 t; cvta.to.shared.u64 t, %1; cvt.u32.u64 %0, t; }" : "=r"(a) : "l"(p));
    return a;
}
__device__ __forceinline__ void cpa16(uint32_t dst_smem, const void* src) {
    asm volatile("cp.async.cg.shared.global [%0], [%1], 16;" :: "r"(dst_smem), "l"(src));
}
__device__ __forceinline__ void cpa_commit() { asm volatile("cp.async.commit_group;"); }
__device__ __forceinline__ void cpa_wait0()  { asm volatile("cp.async.wait_group 0;" ::: "memory"); }

__device__ __forceinline__ void flag_release(unsigned long long* p, unsigned long long v) {
    asm volatile("st.release.gpu.global.u64 [%0], %1;" :: "l"(p), "l"(v) : "memory");
}
__device__ __forceinline__ unsigned long long flag_acquire(const unsigned long long* p) {
    unsigned long long v;
    asm volatile("ld.acquire.gpu.global.u64 %0, [%1];" : "=l"(v) : "l"(p) : "memory");
    return v;
}

__device__ __forceinline__ void mma16816(float* c,
    uint32_t a0, uint32_t a1, uint32_t a2, uint32_t a3, uint32_t b0, uint32_t b1)
{
    asm volatile(
        "mma.sync.aligned.m16n8k16.row.col.f32.f16.f16.f32 "
        "{%0,%1,%2,%3}, {%4,%5,%6,%7}, {%8,%9}, {%0,%1,%2,%3};"
        : "+f"(c[0]), "+f"(c[1]), "+f"(c[2]), "+f"(c[3])
        : "r"(a0), "r"(a1), "r"(a2), "r"(a3), "r"(b0), "r"(b1));
}

__device__ __forceinline__ void ldsm4(uint32_t& a0, uint32_t& a1, uint32_t& a2, uint32_t& a3,
                                      uint32_t addr)
{
    asm volatile("ldmatrix.sync.aligned.m8n8.x4.shared.b16 {%0,%1,%2,%3}, [%4];"
                 : "=r"(a0), "=r"(a1), "=r"(a2), "=r"(a3) : "r"(addr));
}

__device__ __forceinline__ float sig_(float x)  { return __fdividef(1.f, 1.f + __expf(-x)); }
__device__ __forceinline__ float tanh_(float x) { return 1.f - 2.f * __fdividef(1.f, __expf(2.f * x) + 1.f); }

// ---------------- prep: transpose W_ih, fold biases ----------------
__global__ void lstm_prep(const float* __restrict__ Wih1,
                          const float* __restrict__ bih1,
                          const float* __restrict__ bhh1,
                          const float* __restrict__ Wih2,
                          const float* __restrict__ bih2,
                          const float* __restrict__ bhh2)
{
    int i = blockIdx.x * blockDim.x + threadIdx.x;
    if (i < Cz * Gz) {
        int g = i / Cz;
        int c = i - g * Cz;
        g_wt1[(size_t)c * Gz + g] = Wih1[(size_t)g * Cz + c];
        g_wt2[(size_t)c * Gz + g] = Wih2[(size_t)g * Cz + c];
    }
    if (i < Gz) {
        g_bias1[i] = bih1[i] + bhh1[i];
        g_bias2[i] = bih2[i] + bhh2[i];
    }
}

// ---------------- prep: pack W_hh into mma.sync B fragments ----------------
// Slice n owns h-cols [16n,16n+16). Warp w (0..7): gate = w>>1, col block = (w&1)*8.
// W row for (w, ncol) = gate*512 + 16n + (w&1)*8 + ncol, ncol = lane>>2.
__global__ void prep_wr(const float* __restrict__ Whh1, const float* __restrict__ Whh2)
{
    int e = blockIdx.x * blockDim.x + threadIdx.x;   // [l][n][w][lane][ks]
    if (e >= 2 * NSLICE * 8 * 32 * 32) return;
    int ks   = e & 31;
    int lane = (e >> 5) & 31;
    int w    = (e >> 10) & 7;
    int n    = (e >> 13) & 31;
    int l    = e >> 18;
    const float* W = l ? Whh2 : Whh1;
    int wrow = (w >> 1) * Hz + n * 16 + (w & 1) * 8 + (lane >> 2);
    int kb   = ks * 16 + (lane & 3) * 2;
    const float* r = W + (size_t)wrow * Hz;
    __half2 v0 = __floats2half2_rn(r[kb],     r[kb + 1]);
    __half2 v1 = __floats2half2_rn(r[kb + 8], r[kb + 9]);
    uint32_t* dst = l ? g_wr2 : g_wr1;
    size_t idx = ((((size_t)n * 8 + w) * 32 + lane) * 32 + ks) * 2;
    dst[idx]     = *(const uint32_t*)&v0;
    dst[idx + 1] = *(const uint32_t*)&v1;
}

// ---------------- xp GEMM (unchanged) ----------------
template<bool XLAYOUT>
__global__ void __launch_bounds__(256)
gemm_xp(const float* __restrict__ A,
        const float* __restrict__ Wt,
        const float* __restrict__ bias,
        float* __restrict__ Cout)
{
    __shared__ float As[16][128];
    __shared__ float Bs[16][128];

    const int m0 = blockIdx.y * 128;
    const int g0 = blockIdx.x * 128;
    const int tid = threadIdx.x;
    const int tx = tid & 15;
    const int ty = tid >> 4;

    float acc[8][8];
#pragma unroll
    for (int i = 0; i < 8; i++)
#pragma unroll
        for (int j = 0; j < 8; j++) acc[i][j] = 0.f;

    for (int k0 = 0; k0 < Cz; k0 += 16) {
        if (XLAYOUT) {
            int c  = tid >> 5;
            int mi = (tid & 31) * 4;
#pragma unroll
            for (int p = 0; p < 2; p++, c += 8) {
                int m = m0 + mi;
                int b = m >> 9;
                int t = m & 511;
                float4 v = *(const float4*)&A[(size_t)b * (Cz * Tz) + (size_t)(k0 + c) * Tz + t];
                *(float4*)&As[c][mi] = v;
            }
        } else {
            int c4 = (tid & 3) * 4;
            int mi = tid >> 2;
#pragma unroll
            for (int p = 0; p < 2; p++, mi += 64) {
                float4 v = *(const float4*)&A[(size_t)(m0 + mi) * Cz + k0 + c4];
                As[c4 + 0][mi] = v.x;
                As[c4 + 1][mi] = v.y;
                As[c4 + 2][mi] = v.z;
                As[c4 + 3][mi] = v.w;
            }
        }
        {
            int c  = tid >> 5;
            int g4 = (tid & 31) * 4;
#pragma unroll
            for (int p = 0; p < 2; p++, c += 8) {
                *(float4*)&Bs[c][g4] = *(const float4*)&Wt[(size_t)(k0 + c) * Gz + g0 + g4];
            }
        }
        __syncthreads();

#pragma unroll
        for (int k = 0; k < 16; k++) {
            float a[8], b[8];
            *(float4*)&a[0] = *(float4*)&As[k][ty * 8];
            *(float4*)&a[4] = *(float4*)&As[k][ty * 8 + 4];
            *(float4*)&b[0] = *(float4*)&Bs[k][tx * 8];
            *(float4*)&b[4] = *(float4*)&Bs[k][tx * 8 + 4];
#pragma unroll
            for (int i = 0; i < 8; i++)
#pragma unroll
                for (int j = 0; j < 8; j++)
                    acc[i][j] += a[i] * b[j];
        }
        __syncthreads();
    }

    float bv[8];
#pragma unroll
    for (int j = 0; j < 8; j++) bv[j] = bias[g0 + tx * 8 + j];

#pragma unroll
    for (int i = 0; i < 8; i++) {
        size_t m = (size_t)(m0 + ty * 8 + i);
#pragma unroll
        for (int j = 0; j < 8; j += 4) {
            float4 v;
            v.x = acc[i][j + 0] + bv[j + 0];
            v.y = acc[i][j + 1] + bv[j + 1];
            v.z = acc[i][j + 2] + bv[j + 2];
            v.w = acc[i][j + 3] + bv[j + 3];
            *(float4*)&Cout[m * Gz + g0 + tx * 8 + j] = v;
        }
    }
}

// ---------------- persistent mma.sync recurrent kernel ----------------
// 128 CTAs = 4 batch groups x 32 col-slices; 256 threads (8 warps) each.
// Group grp owns batch rows [16*grp, 16*grp+16); slice n owns h-cols [16n,16n+16).
// Per step per CTA: gates[16 x 64] = h_grp[16 x 512] @ W'^T  (1 M-tile/warp).
#define HROWB 1040   // 520 halves per padded smem row
__global__ void __launch_bounds__(256, 1)
lstm_rec(const uint32_t* __restrict__ wr,
         const float* __restrict__ xp,
         float* __restrict__ hout)
{
    extern __shared__ __align__(16) char sm[];
    __half* h_s = (__half*)sm;                   // [16][520]  16640 B
    float*  gs  = (float*)(sm + 16 * HROWB);     // [16][80]    5120 B
    const uint32_t hs_base = smem_u32(h_s);

    const int tid  = threadIdx.x;
    const int w    = tid >> 5;
    const int lane = tid & 31;
    const int n    = blockIdx.x & 31;
    const int grp  = blockIdx.x >> 5;

    // ---- register-resident B fragments (64 u32/lane) ----
    uint32_t wB[64];
    {
        const uint4* p = (const uint4*)(wr + (((size_t)n * 8 + w) * 32 + lane) * 64);
#pragma unroll
        for (int q = 0; q < 16; q++) {
            uint4 v = p[q];
            wB[q * 4 + 0] = v.x; wB[q * 4 + 1] = v.y;
            wB[q * 4 + 2] = v.z; wB[q * 4 + 3] = v.w;
        }
    }

    // epilogue mapping: 1 output/thread
    const int em  = tid >> 4;   // batch row within group (0..15)
    const int col = tid & 15;   // h-col within slice
    float creg = 0.f;

    // zero my h0 element
    g_h[grp][0][em * Hz + n * 16 + col] = __float2half(0.f);

    const unsigned long long base = g_flag[grp][n][0];
    __syncthreads();
    if (tid == 0) flag_release(&g_flag[grp][n][0], base + 1ULL);

    // ldmatrix A-frag source address
    const uint32_t a_base = hs_base + (uint32_t)((lane & 15) * HROWB + (lane >> 4) * 16);
    // gs staging indices
    const int crow = lane >> 2;
    const int sc   = (w >> 1) * 16 + (w & 1) * 8 + (lane & 3) * 2;

    for (int t = 0; t < Tz; t++) {
        // ---- barrier: all slices of my group published h(t) ----
        if (tid < NSLICE) {
            while (flag_acquire(&g_flag[grp][tid][0]) < base + 1ULL + (unsigned long long)t) { }
        }
        __syncthreads();

        // ---- cp.async h(t) into SMEM (16 rows x 1024B) ----
        {
            const char* hsrc = (const char*)&g_h[grp][t & 1][0];
#pragma unroll
            for (int q = 0; q < 4; q++) {
                int z = q * 256 + tid;
                cpa16(hs_base + (z >> 6) * HROWB + (z & 63) * 16, hsrc + z * 16);
            }
            cpa_commit();
        }

        // ---- xp prefetch (overlaps cpa wait + MMA) ----
        const float* xb = xp + ((size_t)(grp * 16 + em) * Tz + t) * Gz + n * 16 + col;
        float xq0 = __ldg(xb);
        float xq1 = __ldg(xb + 512);
        float xq2 = __ldg(xb + 1024);
        float xq3 = __ldg(xb + 1536);

        cpa_wait0();
        __syncthreads();

        // ---- MMA: 1 M-tile x 32 k-steps ----
        float c_[4] = {0.f, 0.f, 0.f, 0.f};
#pragma unroll
        for (int ks = 0; ks < 32; ks++) {
            uint32_t a0, a1, a2, a3;
            ldsm4(a0, a1, a2, a3, a_base + (uint32_t)(ks * 32));
            mma16816(c_, a0, a1, a2, a3, wB[ks * 2], wB[ks * 2 + 1]);
        }

        // ---- stage gates ----
        gs[crow * 80 + sc]           = c_[0];
        gs[crow * 80 + sc + 1]       = c_[1];
        gs[(crow + 8) * 80 + sc]     = c_[2];
        gs[(crow + 8) * 80 + sc + 1] = c_[3];
        __syncthreads();

        // ---- epilogue ----
        float gi = gs[em * 80 + col]      + xq0;
        float gf = gs[em * 80 + 16 + col] + xq1;
        float gg = gs[em * 80 + 32 + col] + xq2;
        float go = gs[em * 80 + 48 + col] + xq3;
        float iv = sig_(gi);
        float fv = sig_(gf);
        float gv = tanh_(gg);
        float ov = sig_(go);
        creg = fv * creg + iv * gv;
        float hv = ov * tanh_(creg);

        // publish fp16 h first, release, then fp32 output (off critical path)
        g_h[grp][(t + 1) & 1][em * Hz + n * 16 + col] = __float2half(hv);
        __syncthreads();
        if (tid == 0) flag_release(&g_flag[grp][n][0], base + 2ULL + (unsigned long long)t);
        hout[((size_t)(grp * 16 + em) * Tz + t) * Hz + n * 16 + col] = hv;
    }
}

// ---------------- final transpose: hseq [b][t][c] -> out [b][c][t] ----------
__global__ void __launch_bounds__(256)
transpose_out(const float* __restrict__ hseq, float* __restrict__ out)
{
    __shared__ float smt[32][33];
    const int t0 = blockIdx.x * 32;
    const int c0 = blockIdx.y * 32;
    const int b  = blockIdx.z;
    const int tx = threadIdx.x;
    const int ty = threadIdx.y;

#pragma unroll
    for (int i = 0; i < 4; i++)
        smt[ty + i * 8][tx] = hseq[((size_t)b * Tz + t0 + ty + i * 8) * Hz + c0 + tx];
    __syncthreads();
#pragma unroll
    for (int i = 0; i < 4; i++)
        out[(size_t)b * (Hz * Tz) + (size_t)(c0 + ty + i * 8) * Tz + t0 + tx] = smt[tx][ty + i * 8];
}

// ---------------- host launcher ----------------
extern "C" void kernel_launch(void* const* d_in, const int* in_sizes, int n_in,
                              void* d_out, int out_size)
{
    const float* x     = (const float*)d_in[0];
    const float* W_ih1 = (const float*)d_in[1];
    const float* W_hh1 = (const float*)d_in[2];
    const float* b_ih1 = (const float*)d_in[3];
    const float* b_hh1 = (const float*)d_in[4];
    const float* W_ih2 = (const float*)d_in[5];
    const float* W_hh2 = (const float*)d_in[6];
    const float* b_ih2 = (const float*)d_in[7];
    const float* b_hh2 = (const float*)d_in[8];
    float* out = (float*)d_out;

    float *p_xp, *p_hseq, *p_wt1, *p_wt2, *p_b1, *p_b2;
    uint32_t *p_wr1, *p_wr2;
    cudaGetSymbolAddress((void**)&p_xp,   g_xp);
    cudaGetSymbolAddress((void**)&p_hseq, g_hseq);
    cudaGetSymbolAddress((void**)&p_wt1,  g_wt1);
    cudaGetSymbolAddress((void**)&p_wt2,  g_wt2);
    cudaGetSymbolAddress((void**)&p_b1,   g_bias1);
    cudaGetSymbolAddress((void**)&p_b2,   g_bias2);
    cudaGetSymbolAddress((void**)&p_wr1,  g_wr1);
    cudaGetSymbolAddress((void**)&p_wr2,  g_wr2);

    const int rec_smem = 16 * HROWB + 16 * 80 * 4;  // 21760 B
    cudaFuncSetAttribute(lstm_rec, cudaFuncAttributeMaxDynamicSharedMemorySize, rec_smem);

    // prep
    lstm_prep<<<(Cz * Gz + 255) / 256, 256>>>(W_ih1, b_ih1, b_hh1, W_ih2, b_ih2, b_hh2);
    prep_wr<<<(2 * NSLICE * 8 * 32 * 32 + 255) / 256, 256>>>(W_hh1, W_hh2);

    // xp1 = x^T-view @ W_ih1^T + bias1
    gemm_xp<true><<<dim3(Gz / 128, Mz / 128), 256>>>(x, p_wt1, p_b1, p_xp);

    // recurrence layer 1 -> g_hseq [m][c]
    lstm_rec<<<NGRP * NSLICE, 256, rec_smem>>>(p_wr1, p_xp, p_hseq);

    // xp2 = hseq @ W_ih2^T + bias2
    gemm_xp<false><<<dim3(Gz / 128, Mz / 128), 256>>>(p_hseq, p_wt2, p_b2, p_xp);

    // recurrence layer 2 -> g_hseq [m][c] (overwrites; xp2 already extracted)
    lstm_rec<<<NGRP * NSLICE, 256, rec_smem>>>(p_wr2, p_xp, p_hseq);

    // final transpose -> out (B, H, T)
    transpose_out<<<dim3(Tz / 32, Hz / 32, Bz), dim3(32, 8)>>>(p_hseq, out);
}

// round 9
// speedup vs baseline: 4.6785x; 1.6417x over previous
#include <cuda_runtime.h>
#include <cuda_fp16.h>
#include <math.h>
#include <stdint.h>

// Problem constants
#define Bz 64
#define Tz 512
#define Cz 512
#define Hz 512
#define Gz 2048    // 4*H
#define Mz (Bz*Tz) // 32768
#define NSLICE 32  // h-col slices (CTAs per group)
#define NGRP 4     // batch groups (16 rows each)

// ---------------- device scratch (static, no allocation) ----------------
__device__ float g_xp[(size_t)Mz * Gz];      // [m][g]
__device__ float g_hseq[(size_t)Mz * Hz];    // [m][c] fp32 (layer-2 output)
__device__ __half g_xh[(size_t)Mz * Cz];     // fp16 GEMM input ([m][c]); x, then h1
__device__ __half g_w16a[Gz * Cz];           // W_ih1 fp16 [g][k]
__device__ __half g_w16b[Gz * Cz];           // W_ih2 fp16 [g][k]
__device__ float g_bias1[Gz];
__device__ float g_bias2[Gz];
__device__ uint32_t g_wr1[NSLICE * 8 * 32 * 64];  // recurrent B fragments
__device__ uint32_t g_wr2[NSLICE * 8 * 32 * 64];
__device__ __half g_h[NGRP][2][16 * Hz];     // per-group h fp16 double buffer
__device__ unsigned long long g_flag[NGRP][NSLICE][16];  // padded flags

// ==================== helpers ====================
__device__ __forceinline__ uint32_t smem_u32(const void* p) {
    uint32_t a;
    asm("{ .reg .u64 t; cvta.to.shared.u64 t, %1; cvt.u32.u64 %0, t; }" : "=r"(a) : "l"(p));
    return a;
}
__device__ __forceinline__ void cpa16(uint32_t dst_smem, const void* src) {
    asm volatile("cp.async.cg.shared.global [%0], [%1], 16;" :: "r"(dst_smem), "l"(src));
}
__device__ __forceinline__ void cpa_commit() { asm volatile("cp.async.commit_group;"); }
__device__ __forceinline__ void cpa_wait0()  { asm volatile("cp.async.wait_group 0;" ::: "memory"); }
__device__ __forceinline__ void cpa_wait1()  { asm volatile("cp.async.wait_group 1;" ::: "memory"); }

__device__ __forceinline__ void flag_release(unsigned long long* p, unsigned long long v) {
    asm volatile("st.release.gpu.global.u64 [%0], %1;" :: "l"(p), "l"(v) : "memory");
}
__device__ __forceinline__ unsigned long long flag_acquire(const unsigned long long* p) {
    unsigned long long v;
    asm volatile("ld.acquire.gpu.global.u64 %0, [%1];" : "=l"(v) : "l"(p) : "memory");
    return v;
}

__device__ __forceinline__ void mma16816(float* c,
    uint32_t a0, uint32_t a1, uint32_t a2, uint32_t a3, uint32_t b0, uint32_t b1)
{
    asm volatile(
        "mma.sync.aligned.m16n8k16.row.col.f32.f16.f16.f32 "
        "{%0,%1,%2,%3}, {%4,%5,%6,%7}, {%8,%9}, {%0,%1,%2,%3};"
        : "+f"(c[0]), "+f"(c[1]), "+f"(c[2]), "+f"(c[3])
        : "r"(a0), "r"(a1), "r"(a2), "r"(a3), "r"(b0), "r"(b1));
}

__device__ __forceinline__ void ldsm4(uint32_t& a0, uint32_t& a1, uint32_t& a2, uint32_t& a3,
                                      uint32_t addr)
{
    asm volatile("ldmatrix.sync.aligned.m8n8.x4.shared.b16 {%0,%1,%2,%3}, [%4];"
                 : "=r"(a0), "=r"(a1), "=r"(a2), "=r"(a3) : "r"(addr));
}

__device__ __forceinline__ float sig_(float x)  { return __fdividef(1.f, 1.f + __expf(-x)); }
__device__ __forceinline__ float tanh_(float x) { return 1.f - 2.f * __fdividef(1.f, __expf(2.f * x) + 1.f); }

// ---------------- prep: fp16 weights, fold biases ----------------
__global__ void lstm_prep(const float* __restrict__ Wih1,
                          const float* __restrict__ bih1,
                          const float* __restrict__ bhh1,
                          const float* __restrict__ Wih2,
                          const float* __restrict__ bih2,
                          const float* __restrict__ bhh2)
{
    int i = blockIdx.x * blockDim.x + threadIdx.x;
    if (i < Gz * Cz) {
        g_w16a[i] = __float2half(Wih1[i]);
        g_w16b[i] = __float2half(Wih2[i]);
    }
    if (i < Gz) {
        g_bias1[i] = bih1[i] + bhh1[i];
        g_bias2[i] = bih2[i] + bhh2[i];
    }
}

// ---------------- prep: pack W_hh into mma.sync B fragments ----------------
__global__ void prep_wr(const float* __restrict__ Whh1, const float* __restrict__ Whh2)
{
    int e = blockIdx.x * blockDim.x + threadIdx.x;
    if (e >= 2 * NSLICE * 8 * 32 * 32) return;
    int ks   = e & 31;
    int lane = (e >> 5) & 31;
    int w    = (e >> 10) & 7;
    int n    = (e >> 13) & 31;
    int l    = e >> 18;
    const float* W = l ? Whh2 : Whh1;
    int wrow = (w >> 1) * Hz + n * 16 + (w & 1) * 8 + (lane >> 2);
    int kb   = ks * 16 + (lane & 3) * 2;
    const float* r = W + (size_t)wrow * Hz;
    __half2 v0 = __floats2half2_rn(r[kb],     r[kb + 1]);
    __half2 v1 = __floats2half2_rn(r[kb + 8], r[kb + 9]);
    uint32_t* dst = l ? g_wr2 : g_wr1;
    size_t idx = ((((size_t)n * 8 + w) * 32 + lane) * 32 + ks) * 2;
    dst[idx]     = *(const uint32_t*)&v0;
    dst[idx + 1] = *(const uint32_t*)&v1;
}

// ---------------- convert x (B,C,T) -> fp16 [b*T+t][c] ----------------
__global__ void __launch_bounds__(256)
convert_x(const float* __restrict__ x, __half* __restrict__ xh)
{
    __shared__ float smt[32][33];
    const int t0 = blockIdx.x * 32;
    const int c0 = blockIdx.y * 32;
    const int b  = blockIdx.z;
    const int tx = threadIdx.x;
    const int ty = threadIdx.y;
#pragma unroll
    for (int i = 0; i < 4; i++)
        smt[ty + i * 8][tx] = x[(size_t)b * (Cz * Tz) + (size_t)(c0 + ty + i * 8) * Tz + t0 + tx];
    __syncthreads();
#pragma unroll
    for (int i = 0; i < 4; i++)
        xh[((size_t)b * Tz + t0 + ty + i * 8) * Cz + c0 + tx] = __float2half(smt[tx][ty + i * 8]);
}

// ---------------- fp16 tensor-core xp GEMM ----------------
// C[m][g] = sum_k A[m][k] * W[g][k] + bias[g].  M=32768, N=2048, K=512.
// CTA tile 128x128, K-chunk 32, double-buffered cp.async. 8 warps: 4(M) x 2(N),
// each warp 32x64. fp32 accumulate.
#define BKP 40   // padded halves per SMEM row (80 B)
#define ASZ (128 * BKP * 2)
__global__ void __launch_bounds__(256)
gemm_xp16(const __half* __restrict__ A,
          const __half* __restrict__ Bw,
          const float* __restrict__ bias,
          float* __restrict__ Cout)
{
    __shared__ __half sbuf[2 * 2 * 128 * BKP];   // A[2], B[2]
    const uint32_t s0 = smem_u32(sbuf);

    const int m0 = blockIdx.y * 128;
    const int g0 = blockIdx.x * 128;
    const int tid = threadIdx.x;
    const int w = tid >> 5;
    const int lane = tid & 31;
    const int wm = (w >> 1) * 32;
    const int wn = (w & 1) * 64;

    float c_[2][8][4];
#pragma unroll
    for (int mt = 0; mt < 2; mt++)
#pragma unroll
        for (int q = 0; q < 8; q++)
#pragma unroll
            for (int i = 0; i < 4; i++) c_[mt][q][i] = 0.f;

    // per-thread load slots: z in [0,512) per tile; row=z>>2, seg=z&3
    const int zr0 = tid >> 2, zs0 = tid & 3;          // z = tid
    const int zr1 = (tid + 256) >> 2, zs1 = tid & 3;  // z = tid+256

    // frag addresses (byte)
    const uint32_t a_off = (uint32_t)(((wm + (lane & 15)) * BKP + (lane >> 4) * 8) * 2);
    const uint32_t b_off = (uint32_t)(((wn + ((lane >> 4) & 1) * 8 + (lane & 7)) * BKP
                                      + ((lane >> 3) & 1) * 8) * 2);

    // prologue: load chunk 0 into buf 0
    {
        const __half* Ab = A + (size_t)(m0 + zr0) * Cz + zs0 * 8;
        const __half* Ab1 = A + (size_t)(m0 + zr1) * Cz + zs1 * 8;
        const __half* Bb = Bw + (size_t)(g0 + zr0) * Cz + zs0 * 8;
        const __half* Bb1 = Bw + (size_t)(g0 + zr1) * Cz + zs1 * 8;
        cpa16(s0 + (zr0 * BKP + zs0 * 8) * 2, Ab);
        cpa16(s0 + (zr1 * BKP + zs1 * 8) * 2, Ab1);
        cpa16(s0 + 2 * ASZ + (zr0 * BKP + zs0 * 8) * 2, Bb);
        cpa16(s0 + 2 * ASZ + (zr1 * BKP + zs1 * 8) * 2, Bb1);
        cpa_commit();
    }

    for (int c = 0; c < 16; c++) {
        const int buf = c & 1;
        if (c < 15) {
            const int nb = buf ^ 1;
            const int k0 = (c + 1) * 32;
            cpa16(s0 + nb * ASZ + (zr0 * BKP + zs0 * 8) * 2,
                  A + (size_t)(m0 + zr0) * Cz + k0 + zs0 * 8);
            cpa16(s0 + nb * ASZ + (zr1 * BKP + zs1 * 8) * 2,
                  A + (size_t)(m0 + zr1) * Cz + k0 + zs1 * 8);
            cpa16(s0 + (2 + nb) * ASZ + (zr0 * BKP + zs0 * 8) * 2,
                  Bw + (size_t)(g0 + zr0) * Cz + k0 + zs0 * 8);
            cpa16(s0 + (2 + nb) * ASZ + (zr1 * BKP + zs1 * 8) * 2,
                  Bw + (size_t)(g0 + zr1) * Cz + k0 + zs1 * 8);
            cpa_commit();
            cpa_wait1();
        } else {
            cpa_wait0();
        }
        __syncthreads();

        const uint32_t ab = s0 + buf * ASZ + a_off;
        const uint32_t bb = s0 + (2 + buf) * ASZ + b_off;
#pragma unroll
        for (int ks = 0; ks < 2; ks++) {
            uint32_t a[2][4];
#pragma unroll
            for (int mt = 0; mt < 2; mt++)
                ldsm4(a[mt][0], a[mt][1], a[mt][2], a[mt][3],
                      ab + (uint32_t)(mt * 16 * BKP * 2 + ks * 32));
#pragma unroll
            for (int j = 0; j < 4; j++) {
                uint32_t r0, r1, r2, r3;
                ldsm4(r0, r1, r2, r3, bb + (uint32_t)(j * 16 * BKP * 2 + ks * 32));
                mma16816(c_[0][2 * j],     a[0][0], a[0][1], a[0][2], a[0][3], r0, r1);
                mma16816(c_[1][2 * j],     a[1][0], a[1][1], a[1][2], a[1][3], r0, r1);
                mma16816(c_[0][2 * j + 1], a[0][0], a[0][1], a[0][2], a[0][3], r2, r3);
                mma16816(c_[1][2 * j + 1], a[1][0], a[1][1], a[1][2], a[1][3], r2, r3);
            }
        }
        __syncthreads();
    }

    // epilogue
#pragma unroll
    for (int q = 0; q < 8; q++) {
        const int gc = g0 + wn + q * 8 + (lane & 3) * 2;
        const float bv0 = bias[gc];
        const float bv1 = bias[gc + 1];
#pragma unroll
        for (int mt = 0; mt < 2; mt++) {
            const int r0 = m0 + wm + mt * 16 + (lane >> 2);
            float2 v0 = make_float2(c_[mt][q][0] + bv0, c_[mt][q][1] + bv1);
            float2 v1 = make_float2(c_[mt][q][2] + bv0, c_[mt][q][3] + bv1);
            *(float2*)&Cout[(size_t)r0 * Gz + gc] = v0;
            *(float2*)&Cout[(size_t)(r0 + 8) * Gz + gc] = v1;
        }
    }
}

// ---------------- persistent mma.sync recurrent kernel (as R7) ----------------
#define HROWB 1040
__global__ void __launch_bounds__(256, 1)
lstm_rec(const uint32_t* __restrict__ wr,
         const float* __restrict__ xp,
         float* __restrict__ hout,
         __half* __restrict__ hout16)
{
    extern __shared__ __align__(16) char sm[];
    __half* h_s = (__half*)sm;                   // [16][520]
    float*  gs  = (float*)(sm + 16 * HROWB);     // [16][80]
    const uint32_t hs_base = smem_u32(h_s);

    const int tid  = threadIdx.x;
    const int w    = tid >> 5;
    const int lane = tid & 31;
    const int n    = blockIdx.x & 31;
    const int grp  = blockIdx.x >> 5;

    uint32_t wB[64];
    {
        const uint4* p = (const uint4*)(wr + (((size_t)n * 8 + w) * 32 + lane) * 64);
#pragma unroll
        for (int q = 0; q < 16; q++) {
            uint4 v = p[q];
            wB[q * 4 + 0] = v.x; wB[q * 4 + 1] = v.y;
            wB[q * 4 + 2] = v.z; wB[q * 4 + 3] = v.w;
        }
    }

    const int em  = tid >> 4;
    const int col = tid & 15;
    float creg = 0.f;

    g_h[grp][0][em * Hz + n * 16 + col] = __float2half(0.f);

    const unsigned long long base = g_flag[grp][n][0];
    __syncthreads();
    if (tid == 0) flag_release(&g_flag[grp][n][0], base + 1ULL);

    const uint32_t a_base = hs_base + (uint32_t)((lane & 15) * HROWB + (lane >> 4) * 16);
    const int crow = lane >> 2;
    const int sc   = (w >> 1) * 16 + (w & 1) * 8 + (lane & 3) * 2;

    for (int t = 0; t < Tz; t++) {
        if (tid < NSLICE) {
            while (flag_acquire(&g_flag[grp][tid][0]) < base + 1ULL + (unsigned long long)t) { }
        }
        __syncthreads();

        {
            const char* hsrc = (const char*)&g_h[grp][t & 1][0];
#pragma unroll
            for (int q = 0; q < 4; q++) {
                int z = q * 256 + tid;
                cpa16(hs_base + (z >> 6) * HROWB + (z & 63) * 16, hsrc + z * 16);
            }
            cpa_commit();
        }

        const float* xb = xp + ((size_t)(grp * 16 + em) * Tz + t) * Gz + n * 16 + col;
        float xq0 = __ldg(xb);
        float xq1 = __ldg(xb + 512);
        float xq2 = __ldg(xb + 1024);
        float xq3 = __ldg(xb + 1536);

        cpa_wait0();
        __syncthreads();

        float c_[4] = {0.f, 0.f, 0.f, 0.f};
#pragma unroll
        for (int ks = 0; ks < 32; ks++) {
            uint32_t a0, a1, a2, a3;
            ldsm4(a0, a1, a2, a3, a_base + (uint32_t)(ks * 32));
            mma16816(c_, a0, a1, a2, a3, wB[ks * 2], wB[ks * 2 + 1]);
        }

        gs[crow * 80 + sc]           = c_[0];
        gs[crow * 80 + sc + 1]       = c_[1];
        gs[(crow + 8) * 80 + sc]     = c_[2];
        gs[(crow + 8) * 80 + sc + 1] = c_[3];
        __syncthreads();

        float gi = gs[em * 80 + col]      + xq0;
        float gf = gs[em * 80 + 16 + col] + xq1;
        float gg = gs[em * 80 + 32 + col] + xq2;
        float go = gs[em * 80 + 48 + col] + xq3;
        float iv = sig_(gi);
        float fv = sig_(gf);
        float gv = tanh_(gg);
        float ov = sig_(go);
        creg = fv * creg + iv * gv;
        float hv = ov * tanh_(creg);
        __half hv16 = __float2half(hv);

        g_h[grp][(t + 1) & 1][em * Hz + n * 16 + col] = hv16;
        __syncthreads();
        if (tid == 0) flag_release(&g_flag[grp][n][0], base + 2ULL + (unsigned long long)t);
        const size_t om = ((size_t)(grp * 16 + em) * Tz + t) * Hz + n * 16 + col;
        if (hout16) hout16[om] = hv16;
        if (hout)   hout[om]   = hv;
    }
}

// ---------------- final transpose: hseq [b][t][c] -> out [b][c][t] ----------
__global__ void __launch_bounds__(256)
transpose_out(const float* __restrict__ hseq, float* __restrict__ out)
{
    __shared__ float smt[32][33];
    const int t0 = blockIdx.x * 32;
    const int c0 = blockIdx.y * 32;
    const int b  = blockIdx.z;
    const int tx = threadIdx.x;
    const int ty = threadIdx.y;

#pragma unroll
    for (int i = 0; i < 4; i++)
        smt[ty + i * 8][tx] = hseq[((size_t)b * Tz + t0 + ty + i * 8) * Hz + c0 + tx];
    __syncthreads();
#pragma unroll
    for (int i = 0; i < 4; i++)
        out[(size_t)b * (Hz * Tz) + (size_t)(c0 + ty + i * 8) * Tz + t0 + tx] = smt[tx][ty + i * 8];
}

// ---------------- host launcher ----------------
extern "C" void kernel_launch(void* const* d_in, const int* in_sizes, int n_in,
                              void* d_out, int out_size)
{
    const float* x     = (const float*)d_in[0];
    const float* W_ih1 = (const float*)d_in[1];
    const float* W_hh1 = (const float*)d_in[2];
    const float* b_ih1 = (const float*)d_in[3];
    const float* b_hh1 = (const float*)d_in[4];
    const float* W_ih2 = (const float*)d_in[5];
    const float* W_hh2 = (const float*)d_in[6];
    const float* b_ih2 = (const float*)d_in[7];
    const float* b_hh2 = (const float*)d_in[8];
    float* out = (float*)d_out;

    float *p_xp, *p_hseq, *p_b1, *p_b2;
    __half *p_xh, *p_w16a, *p_w16b;
    uint32_t *p_wr1, *p_wr2;
    cudaGetSymbolAddress((void**)&p_xp,   g_xp);
    cudaGetSymbolAddress((void**)&p_hseq, g_hseq);
    cudaGetSymbolAddress((void**)&p_xh,   g_xh);
    cudaGetSymbolAddress((void**)&p_w16a, g_w16a);
    cudaGetSymbolAddress((void**)&p_w16b, g_w16b);
    cudaGetSymbolAddress((void**)&p_b1,   g_bias1);
    cudaGetSymbolAddress((void**)&p_b2,   g_bias2);
    cudaGetSymbolAddress((void**)&p_wr1,  g_wr1);
    cudaGetSymbolAddress((void**)&p_wr2,  g_wr2);

    const int rec_smem = 16 * HROWB + 16 * 80 * 4;  // 21760 B
    cudaFuncSetAttribute(lstm_rec, cudaFuncAttributeMaxDynamicSharedMemorySize, rec_smem);

    // prep
    lstm_prep<<<(Gz * Cz + 255) / 256, 256>>>(W_ih1, b_ih1, b_hh1, W_ih2, b_ih2, b_hh2);
    prep_wr<<<(2 * NSLICE * 8 * 32 * 32 + 255) / 256, 256>>>(W_hh1, W_hh2);
    convert_x<<<dim3(Tz / 32, Cz / 32, Bz), dim3(32, 8)>>>(x, p_xh);

    // xp1 = x16 @ W_ih1^T + bias1   (tensor cores)
    gemm_xp16<<<dim3(Gz / 128, Mz / 128), 256>>>(p_xh, p_w16a, p_b1, p_xp);

    // recurrence layer 1 -> fp16 hseq into g_xh (x no longer needed)
    lstm_rec<<<NGRP * NSLICE, 256, rec_smem>>>(p_wr1, p_xp, nullptr, p_xh);

    // xp2 = h1_16 @ W_ih2^T + bias2
    gemm_xp16<<<dim3(Gz / 128, Mz / 128), 256>>>(p_xh, p_w16b, p_b2, p_xp);

    // recurrence layer 2 -> fp32 hseq
    lstm_rec<<<NGRP * NSLICE, 256, rec_smem>>>(p_wr2, p_xp, p_hseq, nullptr);

    // final transpose -> out (B, H, T)
    transpose_out<<<dim3(Tz / 32, Hz / 32, Bz), dim3(32, 8)>>>(p_hseq, out);
}

// round 10
// speedup vs baseline: 5.6254x; 1.2024x over previous
#include <cuda_runtime.h>
#include <cuda_fp16.h>
#include <math.h>
#include <stdint.h>

// Problem constants
#define Bz 64
#define Tz 512
#define Cz 512
#define Hz 512
#define Gz 2048    // 4*H
#define Mz (Bz*Tz) // 32768
#define NSLICE 32  // h-col slices (CTAs per group)
#define NGRP 4     // batch groups (16 rows each)
#define K2P 1040   // W2 image row stride (halves)
#define HROWB 1040 // h tile row stride (bytes)

// ---------------- device scratch (static, no allocation) ----------------
__device__ float g_xp[(size_t)Mz * Gz];      // [m][g]  (layer-1 input projections)
__device__ float g_hseq[(size_t)Mz * Hz];    // [m][c]  (layer-2 output, fp32)
__device__ __half g_xh[(size_t)Mz * Cz];     // fp16 x [m][c]
__device__ __half g_w16a[Gz * Cz];           // W_ih1 fp16 [g][k]
__device__ float g_bias1[Gz];
__device__ float g_bias2[Gz];
__device__ uint32_t g_wr1[NSLICE * 8 * 32 * 64];      // W_hh1 B-fragments (2MB)
__device__ __half g_w2img[(size_t)NSLICE * 64 * K2P]; // per-slice [Wih2;Whh2] images
__device__ __half g_h1[NGRP][2][16 * Hz];    // h1 fp16 double buffer
__device__ __half g_h2[NGRP][2][16 * Hz];    // h2 fp16 double buffer
__device__ unsigned long long g_flag[NGRP][NSLICE][16];  // padded flags

// ==================== helpers ====================
__device__ __forceinline__ uint32_t smem_u32(const void* p) {
    uint32_t a;
    asm("{ .reg .u64 t; cvta.to.shared.u64 t, %1; cvt.u32.u64 %0, t; }" : "=r"(a) : "l"(p));
    return a;
}
__device__ __forceinline__ void cpa16(uint32_t dst_smem, const void* src) {
    asm volatile("cp.async.cg.shared.global [%0], [%1], 16;" :: "r"(dst_smem), "l"(src));
}
__device__ __forceinline__ void cpa_commit() { asm volatile("cp.async.commit_group;"); }
__device__ __forceinline__ void cpa_wait0()  { asm volatile("cp.async.wait_group 0;" ::: "memory"); }
__device__ __forceinline__ void cpa_wait1()  { asm volatile("cp.async.wait_group 1;" ::: "memory"); }

__device__ __forceinline__ void flag_release(unsigned long long* p, unsigned long long v) {
    asm volatile("st.release.gpu.global.u64 [%0], %1;" :: "l"(p), "l"(v) : "memory");
}
__device__ __forceinline__ unsigned long long flag_acquire(const unsigned long long* p) {
    unsigned long long v;
    asm volatile("ld.acquire.gpu.global.u64 %0, [%1];" : "=l"(v) : "l"(p) : "memory");
    return v;
}

__device__ __forceinline__ void mma16816(float* c,
    uint32_t a0, uint32_t a1, uint32_t a2, uint32_t a3, uint32_t b0, uint32_t b1)
{
    asm volatile(
        "mma.sync.aligned.m16n8k16.row.col.f32.f16.f16.f32 "
        "{%0,%1,%2,%3}, {%4,%5,%6,%7}, {%8,%9}, {%0,%1,%2,%3};"
        : "+f"(c[0]), "+f"(c[1]), "+f"(c[2]), "+f"(c[3])
        : "r"(a0), "r"(a1), "r"(a2), "r"(a3), "r"(b0), "r"(b1));
}

__device__ __forceinline__ void ldsm4(uint32_t& a0, uint32_t& a1, uint32_t& a2, uint32_t& a3,
                                      uint32_t addr)
{
    asm volatile("ldmatrix.sync.aligned.m8n8.x4.shared.b16 {%0,%1,%2,%3}, [%4];"
                 : "=r"(a0), "=r"(a1), "=r"(a2), "=r"(a3) : "r"(addr));
}

__device__ __forceinline__ float sig_(float x)  { return __fdividef(1.f, 1.f + __expf(-x)); }
__device__ __forceinline__ float tanh_(float x) { return 1.f - 2.f * __fdividef(1.f, __expf(2.f * x) + 1.f); }

// ---------------- prep: fp16 W_ih1, fold biases ----------------
__global__ void lstm_prep(const float* __restrict__ Wih1,
                          const float* __restrict__ bih1,
                          const float* __restrict__ bhh1,
                          const float* __restrict__ bih2,
                          const float* __restrict__ bhh2)
{
    int i = blockIdx.x * blockDim.x + threadIdx.x;
    if (i < Gz * Cz) g_w16a[i] = __float2half(Wih1[i]);
    if (i < Gz) {
        g_bias1[i] = bih1[i] + bhh1[i];
        g_bias2[i] = bih2[i] + bhh2[i];
    }
}

// ---------------- prep: W_hh1 -> mma.sync B fragments ----------------
__global__ void prep_wr(const float* __restrict__ Whh1)
{
    int e = blockIdx.x * blockDim.x + threadIdx.x;
    if (e >= NSLICE * 8 * 32 * 32) return;
    int ks   = e & 31;
    int lane = (e >> 5) & 31;
    int w    = (e >> 10) & 7;
    int n    = e >> 13;
    int wrow = (w >> 1) * Hz + n * 16 + (w & 1) * 8 + (lane >> 2);
    int kb   = ks * 16 + (lane & 3) * 2;
    const float* r = Whh1 + (size_t)wrow * Hz;
    __half2 v0 = __floats2half2_rn(r[kb],     r[kb + 1]);
    __half2 v1 = __floats2half2_rn(r[kb + 8], r[kb + 9]);
    size_t idx = ((((size_t)n * 8 + w) * 32 + lane) * 32 + ks) * 2;
    g_wr1[idx]     = *(const uint32_t*)&v0;
    g_wr1[idx + 1] = *(const uint32_t*)&v1;
}

// ---------------- prep: combined [W_ih2 ; W_hh2] per-slice fp16 image ------
// Slice n, image row q = gate*16 + col  ->  W row gate*512 + n*16 + col.
// k < 512 -> W_ih2[row][k];  k >= 512 -> W_hh2[row][k-512].  Row stride K2P halves.
__global__ void prep_w2img(const float* __restrict__ Wih2, const float* __restrict__ Whh2)
{
    int e = blockIdx.x * blockDim.x + threadIdx.x;   // [n][q][k]
    if (e >= NSLICE * 64 * 1024) return;
    int k = e & 1023;
    int q = (e >> 10) & 63;
    int n = e >> 16;
    int row = (q >> 4) * Hz + n * 16 + (q & 15);
    float v = (k < 512) ? Wih2[(size_t)row * Hz + k] : Whh2[(size_t)row * Hz + (k - 512)];
    g_w2img[((size_t)n * 64 + q) * K2P + k] = __float2half(v);
}

// ---------------- convert x (B,C,T) -> fp16 [b*T+t][c] ----------------
__global__ void __launch_bounds__(256)
convert_x(const float* __restrict__ x, __half* __restrict__ xh)
{
    __shared__ float smt[32][33];
    const int t0 = blockIdx.x * 32;
    const int c0 = blockIdx.y * 32;
    const int b  = blockIdx.z;
    const int tx = threadIdx.x;
    const int ty = threadIdx.y;
#pragma unroll
    for (int i = 0; i < 4; i++)
        smt[ty + i * 8][tx] = x[(size_t)b * (Cz * Tz) + (size_t)(c0 + ty + i * 8) * Tz + t0 + tx];
    __syncthreads();
#pragma unroll
    for (int i = 0; i < 4; i++)
        xh[((size_t)b * Tz + t0 + ty + i * 8) * Cz + c0 + tx] = __float2half(smt[tx][ty + i * 8]);
}

// ---------------- fp16 tensor-core xp GEMM (layer 1 only) ----------------
#define BKP 40
#define ASZ (128 * BKP * 2)
__global__ void __launch_bounds__(256)
gemm_xp16(const __half* __restrict__ A,
          const __half* __restrict__ Bw,
          const float* __restrict__ bias,
          float* __restrict__ Cout)
{
    __shared__ __half sbuf[2 * 2 * 128 * BKP];
    const uint32_t s0 = smem_u32(sbuf);

    const int m0 = blockIdx.y * 128;
    const int g0 = blockIdx.x * 128;
    const int tid = threadIdx.x;
    const int w = tid >> 5;
    const int lane = tid & 31;
    const int wm = (w >> 1) * 32;
    const int wn = (w & 1) * 64;

    float c_[2][8][4];
#pragma unroll
    for (int mt = 0; mt < 2; mt++)
#pragma unroll
        for (int q = 0; q < 8; q++)
#pragma unroll
            for (int i = 0; i < 4; i++) c_[mt][q][i] = 0.f;

    const int zr0 = tid >> 2, zs0 = tid & 3;
    const int zr1 = (tid + 256) >> 2, zs1 = tid & 3;

    const uint32_t a_off = (uint32_t)(((wm + (lane & 15)) * BKP + (lane >> 4) * 8) * 2);
    const uint32_t b_off = (uint32_t)(((wn + ((lane >> 4) & 1) * 8 + (lane & 7)) * BKP
                                      + ((lane >> 3) & 1) * 8) * 2);

    {
        cpa16(s0 + (zr0 * BKP + zs0 * 8) * 2, A + (size_t)(m0 + zr0) * Cz + zs0 * 8);
        cpa16(s0 + (zr1 * BKP + zs1 * 8) * 2, A + (size_t)(m0 + zr1) * Cz + zs1 * 8);
        cpa16(s0 + 2 * ASZ + (zr0 * BKP + zs0 * 8) * 2, Bw + (size_t)(g0 + zr0) * Cz + zs0 * 8);
        cpa16(s0 + 2 * ASZ + (zr1 * BKP + zs1 * 8) * 2, Bw + (size_t)(g0 + zr1) * Cz + zs1 * 8);
        cpa_commit();
    }

    for (int c = 0; c < 16; c++) {
        const int buf = c & 1;
        if (c < 15) {
            const int nb = buf ^ 1;
            const int k0 = (c + 1) * 32;
            cpa16(s0 + nb * ASZ + (zr0 * BKP + zs0 * 8) * 2,
                  A + (size_t)(m0 + zr0) * Cz + k0 + zs0 * 8);
            cpa16(s0 + nb * ASZ + (zr1 * BKP + zs1 * 8) * 2,
                  A + (size_t)(m0 + zr1) * Cz + k0 + zs1 * 8);
            cpa16(s0 + (2 + nb) * ASZ + (zr0 * BKP + zs0 * 8) * 2,
                  Bw + (size_t)(g0 + zr0) * Cz + k0 + zs0 * 8);
            cpa16(s0 + (2 + nb) * ASZ + (zr1 * BKP + zs1 * 8) * 2,
                  Bw + (size_t)(g0 + zr1) * Cz + k0 + zs1 * 8);
            cpa_commit();
            cpa_wait1();
        } else {
            cpa_wait0();
        }
        __syncthreads();

        const uint32_t ab = s0 + buf * ASZ + a_off;
        const uint32_t bb = s0 + (2 + buf) * ASZ + b_off;
#pragma unroll
        for (int ks = 0; ks < 2; ks++) {
            uint32_t a[2][4];
#pragma unroll
            for (int mt = 0; mt < 2; mt++)
                ldsm4(a[mt][0], a[mt][1], a[mt][2], a[mt][3],
                      ab + (uint32_t)(mt * 16 * BKP * 2 + ks * 32));
#pragma unroll
            for (int j = 0; j < 4; j++) {
                uint32_t r0, r1, r2, r3;
                ldsm4(r0, r1, r2, r3, bb + (uint32_t)(j * 16 * BKP * 2 + ks * 32));
                mma16816(c_[0][2 * j],     a[0][0], a[0][1], a[0][2], a[0][3], r0, r1);
                mma16816(c_[1][2 * j],     a[1][0], a[1][1], a[1][2], a[1][3], r0, r1);
                mma16816(c_[0][2 * j + 1], a[0][0], a[0][1], a[0][2], a[0][3], r2, r3);
                mma16816(c_[1][2 * j + 1], a[1][0], a[1][1], a[1][2], a[1][3], r2, r3);
            }
        }
        __syncthreads();
    }

#pragma unroll
    for (int q = 0; q < 8; q++) {
        const int gc = g0 + wn + q * 8 + (lane & 3) * 2;
        const float bv0 = bias[gc];
        const float bv1 = bias[gc + 1];
#pragma unroll
        for (int mt = 0; mt < 2; mt++) {
            const int r0 = m0 + wm + mt * 16 + (lane >> 2);
            float2 v0 = make_float2(c_[mt][q][0] + bv0, c_[mt][q][1] + bv1);
            float2 v1 = make_float2(c_[mt][q][2] + bv0, c_[mt][q][3] + bv1);
            *(float2*)&Cout[(size_t)r0 * Gz + gc] = v0;
            *(float2*)&Cout[(size_t)(r0 + 8) * Gz + gc] = v1;
        }
    }
}

// ---------------- fused 2-layer persistent recurrent kernel ----------------
// 128 CTAs = 4 groups x 32 slices; 256 threads. Round r (0..512):
//   layer1: h1(r)   = LSTM(xp1(r),  h1(r-1) @ W_hh1)          [skip store r=512]
//   layer2: h2(r-1) = LSTM(bias2 + h1(r-1)@Wih2 + h2(r-2)@Whh2) [skip r=0]
// SMEM: W2 image 133120 | h1 16640 | h2 16640 | gs1 5120 | gs2 5120 = 176640 B
#define W2_OFF 0
#define H1_OFF 133120
#define H2_OFF 149760
#define GS1_OFF 166400
#define GS2_OFF 171520
#define REC_SMEM 176640
__global__ void __launch_bounds__(256, 1)
lstm_rec2(const uint32_t* __restrict__ wr1,
          const __half* __restrict__ w2img,
          const float* __restrict__ xp,
          float* __restrict__ hseq)
{
    extern __shared__ __align__(16) char sm[];
    const uint32_t sbase = smem_u32(sm);
    float* gs1 = (float*)(sm + GS1_OFF);
    float* gs2 = (float*)(sm + GS2_OFF);

    const int tid  = threadIdx.x;
    const int w    = tid >> 5;
    const int lane = tid & 31;
    const int n    = blockIdx.x & 31;
    const int grp  = blockIdx.x >> 5;

    // ---- W_hh1 register fragments ----
    uint32_t wB1[64];
    {
        const uint4* p = (const uint4*)(wr1 + (((size_t)n * 8 + w) * 32 + lane) * 64);
#pragma unroll
        for (int q = 0; q < 16; q++) {
            uint4 v = p[q];
            wB1[q * 4 + 0] = v.x; wB1[q * 4 + 1] = v.y;
            wB1[q * 4 + 2] = v.z; wB1[q * 4 + 3] = v.w;
        }
    }

    // ---- W2 image into SMEM (one-time, 133120 B) ----
    {
        const char* src = (const char*)w2img + (size_t)n * (64 * K2P * 2);
        for (int z = tid; z < 8320; z += 256)
            cpa16(sbase + W2_OFF + z * 16, src + (size_t)z * 16);
        cpa_commit();
    }

    // epilogue mapping
    const int em   = tid >> 4;        // batch row within group
    const int col  = tid & 15;        // h-col within slice
    const int gcol = n * 16 + col;    // global h-col
    float c1reg = 0.f, c2reg = 0.f;
    const float b2i = g_bias2[0 * Hz + gcol];
    const float b2f = g_bias2[1 * Hz + gcol];
    const float b2g = g_bias2[2 * Hz + gcol];
    const float b2o = g_bias2[3 * Hz + gcol];

    // zero h1 buf0, h2 buf0, h2 buf1
    g_h1[grp][0][em * Hz + gcol] = __float2half(0.f);
    g_h2[grp][0][em * Hz + gcol] = __float2half(0.f);
    g_h2[grp][1][em * Hz + gcol] = __float2half(0.f);

    const unsigned long long base = g_flag[grp][n][0];
    __syncthreads();
    if (tid == 0) flag_release(&g_flag[grp][n][0], base + 1ULL);

    // ldmatrix addressing
    const uint32_t a1_base = sbase + H1_OFF + (uint32_t)((lane & 15) * HROWB + (lane >> 4) * 16);
    const uint32_t a2_base = sbase + H2_OFF + (uint32_t)((lane & 15) * HROWB + (lane >> 4) * 16);
    const uint32_t b2_base = sbase + W2_OFF +
        (uint32_t)((8 * w + (lane & 7)) * (K2P * 2) + (lane >> 3) * 16);
    const int crow = lane >> 2;
    const int sc   = (w >> 1) * 16 + (w & 1) * 8 + (lane & 3) * 2;

    for (int r = 0; r <= Tz; r++) {
        // ---- barrier: all slices finished round r-1 ----
        if (tid < NSLICE) {
            while (flag_acquire(&g_flag[grp][tid][0]) < base + 1ULL + (unsigned long long)r) { }
        }
        __syncthreads();

        // ---- cp.async h1(r-1), h2(r-2) tiles (16 KB each) ----
        {
            const char* s1 = (const char*)&g_h1[grp][r & 1][0];
            const char* s2 = (const char*)&g_h2[grp][r & 1][0];
#pragma unroll
            for (int q = 0; q < 4; q++) {
                int z = q * 256 + tid;
                uint32_t off = (uint32_t)((z >> 6) * HROWB + (z & 63) * 16);
                cpa16(sbase + H1_OFF + off, s1 + z * 16);
                cpa16(sbase + H2_OFF + off, s2 + z * 16);
            }
            cpa_commit();
        }

        // ---- xp1 prefetch (t = r, clamped) ----
        const int tq = (r < Tz) ? r : (Tz - 1);
        const float* xb = xp + ((size_t)(grp * 16 + em) * Tz + tq) * Gz + gcol;
        float xq0 = __ldg(xb);
        float xq1 = __ldg(xb + 512);
        float xq2 = __ldg(xb + 1024);
        float xq3 = __ldg(xb + 1536);

        cpa_wait0();
        __syncthreads();

        // ---- MMA ----
        float c1_[4] = {0.f, 0.f, 0.f, 0.f};
        float c2_[4] = {0.f, 0.f, 0.f, 0.f};

        // part 1: A = h1(r-1), k-steps 0..31  (layer1 regs-B + layer2 smem-B)
#pragma unroll
        for (int ks2 = 0; ks2 < 16; ks2++) {
            uint32_t b0, b1, b2, b3;
            ldsm4(b0, b1, b2, b3, b2_base + (uint32_t)(ks2 * 64));
            uint32_t a0, a1, a2, a3;
            ldsm4(a0, a1, a2, a3, a1_base + (uint32_t)((2 * ks2) * 32));
            mma16816(c1_, a0, a1, a2, a3, wB1[4 * ks2 + 0], wB1[4 * ks2 + 1]);
            mma16816(c2_, a0, a1, a2, a3, b0, b1);
            ldsm4(a0, a1, a2, a3, a1_base + (uint32_t)((2 * ks2 + 1) * 32));
            mma16816(c1_, a0, a1, a2, a3, wB1[4 * ks2 + 2], wB1[4 * ks2 + 3]);
            mma16816(c2_, a0, a1, a2, a3, b2, b3);
        }
        // part 2: A = h2(r-2), k-steps 32..63 (layer2 only)
#pragma unroll
        for (int ks2 = 0; ks2 < 16; ks2++) {
            uint32_t b0, b1, b2, b3;
            ldsm4(b0, b1, b2, b3, b2_base + (uint32_t)((16 + ks2) * 64));
            uint32_t a0, a1, a2, a3;
            ldsm4(a0, a1, a2, a3, a2_base + (uint32_t)((2 * ks2) * 32));
            mma16816(c2_, a0, a1, a2, a3, b0, b1);
            ldsm4(a0, a1, a2, a3, a2_base + (uint32_t)((2 * ks2 + 1) * 32));
            mma16816(c2_, a0, a1, a2, a3, b2, b3);
        }

        // ---- stage gates ----
        gs1[crow * 80 + sc]           = c1_[0];
        gs1[crow * 80 + sc + 1]       = c1_[1];
        gs1[(crow + 8) * 80 + sc]     = c1_[2];
        gs1[(crow + 8) * 80 + sc + 1] = c1_[3];
        gs2[crow * 80 + sc]           = c2_[0];
        gs2[crow * 80 + sc + 1]       = c2_[1];
        gs2[(crow + 8) * 80 + sc]     = c2_[2];
        gs2[(crow + 8) * 80 + sc + 1] = c2_[3];
        __syncthreads();

        // ---- epilogues ----
        float h2v = 0.f;
        bool do2 = (r > 0);
        if (r < Tz) {
            float gi = gs1[em * 80 + col]      + xq0;
            float gf = gs1[em * 80 + 16 + col] + xq1;
            float gg = gs1[em * 80 + 32 + col] + xq2;
            float go = gs1[em * 80 + 48 + col] + xq3;
            float iv = sig_(gi), fv = sig_(gf), gv = tanh_(gg), ov = sig_(go);
            c1reg = fv * c1reg + iv * gv;
            float h1v = ov * tanh_(c1reg);
            g_h1[grp][(r + 1) & 1][em * Hz + gcol] = __float2half(h1v);
        }
        if (do2) {
            float gi = gs2[em * 80 + col]      + b2i;
            float gf = gs2[em * 80 + 16 + col] + b2f;
            float gg = gs2[em * 80 + 32 + col] + b2g;
            float go = gs2[em * 80 + 48 + col] + b2o;
            float iv = sig_(gi), fv = sig_(gf), gv = tanh_(gg), ov = sig_(go);
            c2reg = fv * c2reg + iv * gv;
            h2v = ov * tanh_(c2reg);
            g_h2[grp][(r + 1) & 1][em * Hz + gcol] = __float2half(h2v);
        }
        __syncthreads();
        if (tid == 0) flag_release(&g_flag[grp][n][0], base + 2ULL + (unsigned long long)r);
        // fp32 output store off the critical path
        if (do2)
            hseq[((size_t)(grp * 16 + em) * Tz + (r - 1)) * Hz + gcol] = h2v;
    }
}

// ---------------- final transpose: hseq [b][t][c] -> out [b][c][t] ----------
__global__ void __launch_bounds__(256)
transpose_out(const float* __restrict__ hseq, float* __restrict__ out)
{
    __shared__ float smt[32][33];
    const int t0 = blockIdx.x * 32;
    const int c0 = blockIdx.y * 32;
    const int b  = blockIdx.z;
    const int tx = threadIdx.x;
    const int ty = threadIdx.y;

#pragma unroll
    for (int i = 0; i < 4; i++)
        smt[ty + i * 8][tx] = hseq[((size_t)b * Tz + t0 + ty + i * 8) * Hz + c0 + tx];
    __syncthreads();
#pragma unroll
    for (int i = 0; i < 4; i++)
        out[(size_t)b * (Hz * Tz) + (size_t)(c0 + ty + i * 8) * Tz + t0 + tx] = smt[tx][ty + i * 8];
}

// ---------------- host launcher ----------------
extern "C" void kernel_launch(void* const* d_in, const int* in_sizes, int n_in,
                              void* d_out, int out_size)
{
    const float* x     = (const float*)d_in[0];
    const float* W_ih1 = (const float*)d_in[1];
    const float* W_hh1 = (const float*)d_in[2];
    const float* b_ih1 = (const float*)d_in[3];
    const float* b_hh1 = (const float*)d_in[4];
    const float* W_ih2 = (const float*)d_in[5];
    const float* W_hh2 = (const float*)d_in[6];
    const float* b_ih2 = (const float*)d_in[7];
    const float* b_hh2 = (const float*)d_in[8];
    float* out = (float*)d_out;

    float *p_xp, *p_hseq, *p_b1;
    __half *p_xh, *p_w16a, *p_w2img;
    uint32_t *p_wr1;
    cudaGetSymbolAddress((void**)&p_xp,    g_xp);
    cudaGetSymbolAddress((void**)&p_hseq,  g_hseq);
    cudaGetSymbolAddress((void**)&p_xh,    g_xh);
    cudaGetSymbolAddress((void**)&p_w16a,  g_w16a);
    cudaGetSymbolAddress((void**)&p_b1,    g_bias1);
    cudaGetSymbolAddress((void**)&p_wr1,   g_wr1);
    cudaGetSymbolAddress((void**)&p_w2img, g_w2img);

    cudaFuncSetAttribute(lstm_rec2, cudaFuncAttributeMaxDynamicSharedMemorySize, REC_SMEM);

    // prep
    lstm_prep<<<(Gz * Cz + 255) / 256, 256>>>(W_ih1, b_ih1, b_hh1, b_ih2, b_hh2);
    prep_wr<<<(NSLICE * 8 * 32 * 32 + 255) / 256, 256>>>(W_hh1);
    prep_w2img<<<(NSLICE * 64 * 1024 + 255) / 256, 256>>>(W_ih2, W_hh2);
    convert_x<<<dim3(Tz / 32, Cz / 32, Bz), dim3(32, 8)>>>(x, p_xh);

    // xp1 = x16 @ W_ih1^T + bias1
    gemm_xp16<<<dim3(Gz / 128, Mz / 128), 256>>>(p_xh, p_w16a, p_b1, p_xp);

    // fused 2-layer recurrence -> g_hseq [m][c]
    lstm_rec2<<<NGRP * NSLICE, 256, REC_SMEM>>>(p_wr1, p_w2img, p_xp, p_hseq);

    // final transpose -> out (B, H, T)
    transpose_out<<<dim3(Tz / 32, Hz / 32, Bz), dim3(32, 8)>>>(p_hseq, out);
}

// round 11
// speedup vs baseline: 6.6509x; 1.1823x over previous
#include <cuda_runtime.h>
#include <cuda_fp16.h>
#include <math.h>
#include <stdint.h>

// Problem constants
#define Bz 64
#define Tz 512
#define Cz 512
#define Hz 512
#define Gz 2048    // 4*H
#define Mz (Bz*Tz) // 32768
#define NSLICE 32  // h-col slices (CTAs per group)
#define NGRP 4     // batch groups (16 rows each)
#define K2P 520    // W_hh2 image row stride (halves) -> 1040 B, conflict-free
#define HROWB 1040 // h tile row stride (bytes), conflict-free

// ---------------- device scratch (static, no allocation) ----------------
__device__ float g_xp[(size_t)Mz * Gz];      // [m][g]
__device__ float g_hseq[(size_t)Mz * Hz];    // [m][c]
__device__ __half g_xh[(size_t)Mz * Cz];     // fp16 x [m][c]
__device__ __half g_w16a[Gz * Cz];           // W_ih1 fp16 [g][k]
__device__ float g_bias1[Gz];
__device__ float g_bias2[Gz];
__device__ uint32_t g_wr1[NSLICE * 8 * 32 * 64];      // W_hh1 B-fragments
__device__ uint32_t g_wr2[NSLICE * 8 * 32 * 64];      // W_ih2 B-fragments
__device__ __half g_w2img[(size_t)NSLICE * 64 * K2P]; // per-slice W_hh2 images
__device__ __half g_h1[NGRP][2][16 * Hz];    // h1 fp16 double buffer
__device__ __half g_h2[NGRP][2][16 * Hz];    // h2 fp16 double buffer
__device__ unsigned long long g_flag[NGRP][NSLICE][16];  // padded flags

// ==================== helpers ====================
__device__ __forceinline__ uint32_t smem_u32(const void* p) {
    uint32_t a;
    asm("{ .reg .u64 t; cvta.to.shared.u64 t, %1; cvt.u32.u64 %0, t; }" : "=r"(a) : "l"(p));
    return a;
}
__device__ __forceinline__ void cpa16(uint32_t dst_smem, const void* src) {
    asm volatile("cp.async.cg.shared.global [%0], [%1], 16;" :: "r"(dst_smem), "l"(src));
}
__device__ __forceinline__ void cpa_commit() { asm volatile("cp.async.commit_group;"); }
__device__ __forceinline__ void cpa_wait0()  { asm volatile("cp.async.wait_group 0;" ::: "memory"); }
__device__ __forceinline__ void cpa_wait1()  { asm volatile("cp.async.wait_group 1;" ::: "memory"); }

__device__ __forceinline__ void flag_release(unsigned long long* p, unsigned long long v) {
    asm volatile("st.release.gpu.global.u64 [%0], %1;" :: "l"(p), "l"(v) : "memory");
}
__device__ __forceinline__ unsigned long long flag_acquire(const unsigned long long* p) {
    unsigned long long v;
    asm volatile("ld.acquire.gpu.global.u64 %0, [%1];" : "=l"(v) : "l"(p) : "memory");
    return v;
}

__device__ __forceinline__ void mma16816(float* c,
    uint32_t a0, uint32_t a1, uint32_t a2, uint32_t a3, uint32_t b0, uint32_t b1)
{
    asm volatile(
        "mma.sync.aligned.m16n8k16.row.col.f32.f16.f16.f32 "
        "{%0,%1,%2,%3}, {%4,%5,%6,%7}, {%8,%9}, {%0,%1,%2,%3};"
        : "+f"(c[0]), "+f"(c[1]), "+f"(c[2]), "+f"(c[3])
        : "r"(a0), "r"(a1), "r"(a2), "r"(a3), "r"(b0), "r"(b1));
}

__device__ __forceinline__ void ldsm4(uint32_t& a0, uint32_t& a1, uint32_t& a2, uint32_t& a3,
                                      uint32_t addr)
{
    asm volatile("ldmatrix.sync.aligned.m8n8.x4.shared.b16 {%0,%1,%2,%3}, [%4];"
                 : "=r"(a0), "=r"(a1), "=r"(a2), "=r"(a3) : "r"(addr));
}

__device__ __forceinline__ float sig_(float x)  { return __fdividef(1.f, 1.f + __expf(-x)); }
__device__ __forceinline__ float tanh_(float x) { return 1.f - 2.f * __fdividef(1.f, __expf(2.f * x) + 1.f); }

// ---------------- prep: fp16 W_ih1, fold biases ----------------
__global__ void lstm_prep(const float* __restrict__ Wih1,
                          const float* __restrict__ bih1,
                          const float* __restrict__ bhh1,
                          const float* __restrict__ bih2,
                          const float* __restrict__ bhh2)
{
    int i = blockIdx.x * blockDim.x + threadIdx.x;
    if (i < Gz * Cz) g_w16a[i] = __float2half(Wih1[i]);
    if (i < Gz) {
        g_bias1[i] = bih1[i] + bhh1[i];
        g_bias2[i] = bih2[i] + bhh2[i];
    }
}

// ---------------- prep: W_hh1 / W_ih2 -> mma.sync B fragments ----------------
__global__ void prep_wr(const float* __restrict__ Whh1, const float* __restrict__ Wih2)
{
    int e = blockIdx.x * blockDim.x + threadIdx.x;
    if (e >= 2 * NSLICE * 8 * 32 * 32) return;
    int ks   = e & 31;
    int lane = (e >> 5) & 31;
    int w    = (e >> 10) & 7;
    int n    = (e >> 13) & 31;
    int l    = e >> 18;
    const float* W = l ? Wih2 : Whh1;
    int wrow = (w >> 1) * Hz + n * 16 + (w & 1) * 8 + (lane >> 2);
    int kb   = ks * 16 + (lane & 3) * 2;
    const float* r = W + (size_t)wrow * Hz;
    __half2 v0 = __floats2half2_rn(r[kb],     r[kb + 1]);
    __half2 v1 = __floats2half2_rn(r[kb + 8], r[kb + 9]);
    uint32_t* dst = l ? g_wr2 : g_wr1;
    size_t idx = ((((size_t)n * 8 + w) * 32 + lane) * 32 + ks) * 2;
    dst[idx]     = *(const uint32_t*)&v0;
    dst[idx + 1] = *(const uint32_t*)&v1;
}

// ---------------- prep: W_hh2 per-slice fp16 image (stride K2P) -----------
__global__ void prep_w2img(const float* __restrict__ Whh2)
{
    int e = blockIdx.x * blockDim.x + threadIdx.x;   // [n][q][k]
    if (e >= NSLICE * 64 * 512) return;
    int k = e & 511;
    int q = (e >> 9) & 63;
    int n = e >> 15;
    int row = (q >> 4) * Hz + n * 16 + (q & 15);
    g_w2img[((size_t)n * 64 + q) * K2P + k] = __float2half(Whh2[(size_t)row * Hz + k]);
}

// ---------------- convert x (B,C,T) -> fp16 [b*T+t][c] ----------------
__global__ void __launch_bounds__(256)
convert_x(const float* __restrict__ x, __half* __restrict__ xh)
{
    __shared__ float smt[32][33];
    const int t0 = blockIdx.x * 32;
    const int c0 = blockIdx.y * 32;
    const int b  = blockIdx.z;
    const int tx = threadIdx.x;
    const int ty = threadIdx.y;
#pragma unroll
    for (int i = 0; i < 4; i++)
        smt[ty + i * 8][tx] = x[(size_t)b * (Cz * Tz) + (size_t)(c0 + ty + i * 8) * Tz + t0 + tx];
    __syncthreads();
#pragma unroll
    for (int i = 0; i < 4; i++)
        xh[((size_t)b * Tz + t0 + ty + i * 8) * Cz + c0 + tx] = __float2half(smt[tx][ty + i * 8]);
}

// ---------------- fp16 tensor-core xp GEMM (layer 1 only) ----------------
#define BKP 40
#define ASZ (128 * BKP * 2)
__global__ void __launch_bounds__(256)
gemm_xp16(const __half* __restrict__ A,
          const __half* __restrict__ Bw,
          const float* __restrict__ bias,
          float* __restrict__ Cout)
{
    __shared__ __half sbuf[2 * 2 * 128 * BKP];
    const uint32_t s0 = smem_u32(sbuf);

    const int m0 = blockIdx.y * 128;
    const int g0 = blockIdx.x * 128;
    const int tid = threadIdx.x;
    const int w = tid >> 5;
    const int lane = tid & 31;
    const int wm = (w >> 1) * 32;
    const int wn = (w & 1) * 64;

    float c_[2][8][4];
#pragma unroll
    for (int mt = 0; mt < 2; mt++)
#pragma unroll
        for (int q = 0; q < 8; q++)
#pragma unroll
            for (int i = 0; i < 4; i++) c_[mt][q][i] = 0.f;

    const int zr0 = tid >> 2, zs0 = tid & 3;
    const int zr1 = (tid + 256) >> 2, zs1 = tid & 3;

    const uint32_t a_off = (uint32_t)(((wm + (lane & 15)) * BKP + (lane >> 4) * 8) * 2);
    const uint32_t b_off = (uint32_t)(((wn + ((lane >> 4) & 1) * 8 + (lane & 7)) * BKP
                                      + ((lane >> 3) & 1) * 8) * 2);

    {
        cpa16(s0 + (zr0 * BKP + zs0 * 8) * 2, A + (size_t)(m0 + zr0) * Cz + zs0 * 8);
        cpa16(s0 + (zr1 * BKP + zs1 * 8) * 2, A + (size_t)(m0 + zr1) * Cz + zs1 * 8);
        cpa16(s0 + 2 * ASZ + (zr0 * BKP + zs0 * 8) * 2, Bw + (size_t)(g0 + zr0) * Cz + zs0 * 8);
        cpa16(s0 + 2 * ASZ + (zr1 * BKP + zs1 * 8) * 2, Bw + (size_t)(g0 + zr1) * Cz + zs1 * 8);
        cpa_commit();
    }

    for (int c = 0; c < 16; c++) {
        const int buf = c & 1;
        if (c < 15) {
            const int nb = buf ^ 1;
            const int k0 = (c + 1) * 32;
            cpa16(s0 + nb * ASZ + (zr0 * BKP + zs0 * 8) * 2,
                  A + (size_t)(m0 + zr0) * Cz + k0 + zs0 * 8);
            cpa16(s0 + nb * ASZ + (zr1 * BKP + zs1 * 8) * 2,
                  A + (size_t)(m0 + zr1) * Cz + k0 + zs1 * 8);
            cpa16(s0 + (2 + nb) * ASZ + (zr0 * BKP + zs0 * 8) * 2,
                  Bw + (size_t)(g0 + zr0) * Cz + k0 + zs0 * 8);
            cpa16(s0 + (2 + nb) * ASZ + (zr1 * BKP + zs1 * 8) * 2,
                  Bw + (size_t)(g0 + zr1) * Cz + k0 + zs1 * 8);
            cpa_commit();
            cpa_wait1();
        } else {
            cpa_wait0();
        }
        __syncthreads();

        const uint32_t ab = s0 + buf * ASZ + a_off;
        const uint32_t bb = s0 + (2 + buf) * ASZ + b_off;
#pragma unroll
        for (int ks = 0; ks < 2; ks++) {
            uint32_t a[2][4];
#pragma unroll
            for (int mt = 0; mt < 2; mt++)
                ldsm4(a[mt][0], a[mt][1], a[mt][2], a[mt][3],
                      ab + (uint32_t)(mt * 16 * BKP * 2 + ks * 32));
#pragma unroll
            for (int j = 0; j < 4; j++) {
                uint32_t r0, r1, r2, r3;
                ldsm4(r0, r1, r2, r3, bb + (uint32_t)(j * 16 * BKP * 2 + ks * 32));
                mma16816(c_[0][2 * j],     a[0][0], a[0][1], a[0][2], a[0][3], r0, r1);
                mma16816(c_[1][2 * j],     a[1][0], a[1][1], a[1][2], a[1][3], r0, r1);
                mma16816(c_[0][2 * j + 1], a[0][0], a[0][1], a[0][2], a[0][3], r2, r3);
                mma16816(c_[1][2 * j + 1], a[1][0], a[1][1], a[1][2], a[1][3], r2, r3);
            }
        }
        __syncthreads();
    }

#pragma unroll
    for (int q = 0; q < 8; q++) {
        const int gc = g0 + wn + q * 8 + (lane & 3) * 2;
        const float bv0 = bias[gc];
        const float bv1 = bias[gc + 1];
#pragma unroll
        for (int mt = 0; mt < 2; mt++) {
            const int r0 = m0 + wm + mt * 16 + (lane >> 2);
            float2 v0 = make_float2(c_[mt][q][0] + bv0, c_[mt][q][1] + bv1);
            float2 v1 = make_float2(c_[mt][q][2] + bv0, c_[mt][q][3] + bv1);
            *(float2*)&Cout[(size_t)r0 * Gz + gc] = v0;
            *(float2*)&Cout[(size_t)(r0 + 8) * Gz + gc] = v1;
        }
    }
}

// ---------------- fused 2-layer persistent recurrent kernel ----------------
// SMEM: Whh2 img 66560 | h1 16640 | h2 16640 | gs1 5120 | gs2 5120 = 110080 B
#define W2_OFF 0
#define H1_OFF 66560
#define H2_OFF 83200
#define GS1_OFF 99840
#define GS2_OFF 104960
#define REC_SMEM 110080
__global__ void __launch_bounds__(256, 1)
lstm_rec2(const uint32_t* __restrict__ wr1,
          const uint32_t* __restrict__ wr2,
          const __half* __restrict__ w2img,
          const float* __restrict__ xp,
          float* __restrict__ hseq)
{
    extern __shared__ __align__(16) char sm[];
    const uint32_t sbase = smem_u32(sm);
    float* gs1 = (float*)(sm + GS1_OFF);
    float* gs2 = (float*)(sm + GS2_OFF);

    const int tid  = threadIdx.x;
    const int w    = tid >> 5;
    const int lane = tid & 31;
    const int n    = blockIdx.x & 31;
    const int grp  = blockIdx.x >> 5;

    // ---- W_hh1 + W_ih2 register fragments (64 + 64 u32) ----
    uint32_t wB1[64], wB2[64];
    {
        const uint4* p1 = (const uint4*)(wr1 + (((size_t)n * 8 + w) * 32 + lane) * 64);
        const uint4* p2 = (const uint4*)(wr2 + (((size_t)n * 8 + w) * 32 + lane) * 64);
#pragma unroll
        for (int q = 0; q < 16; q++) {
            uint4 v1 = p1[q];
            wB1[q * 4 + 0] = v1.x; wB1[q * 4 + 1] = v1.y;
            wB1[q * 4 + 2] = v1.z; wB1[q * 4 + 3] = v1.w;
            uint4 v2 = p2[q];
            wB2[q * 4 + 0] = v2.x; wB2[q * 4 + 1] = v2.y;
            wB2[q * 4 + 2] = v2.z; wB2[q * 4 + 3] = v2.w;
        }
    }

    // ---- W_hh2 image into SMEM (one-time, 66560 B) ----
    {
        const char* src = (const char*)w2img + (size_t)n * (64 * K2P * 2);
        for (int z = tid; z < 4160; z += 256)
            cpa16(sbase + W2_OFF + z * 16, src + (size_t)z * 16);
        cpa_commit();
    }

    // epilogue mapping
    const int em   = tid >> 4;
    const int col  = tid & 15;
    const int gcol = n * 16 + col;
    float c1reg = 0.f, c2reg = 0.f;
    const float b2i = g_bias2[0 * Hz + gcol];
    const float b2f = g_bias2[1 * Hz + gcol];
    const float b2g = g_bias2[2 * Hz + gcol];
    const float b2o = g_bias2[3 * Hz + gcol];

    g_h1[grp][0][em * Hz + gcol] = __float2half(0.f);
    g_h2[grp][0][em * Hz + gcol] = __float2half(0.f);
    g_h2[grp][1][em * Hz + gcol] = __float2half(0.f);

    const unsigned long long base = g_flag[grp][n][0];
    __syncthreads();
    if (tid == 0) flag_release(&g_flag[grp][n][0], base + 1ULL);

    // ldmatrix addressing (all strides 65*16B -> conflict-free)
    const uint32_t a1_base = sbase + H1_OFF + (uint32_t)((lane & 15) * HROWB + (lane >> 4) * 16);
    const uint32_t a2_base = sbase + H2_OFF + (uint32_t)((lane & 15) * HROWB + (lane >> 4) * 16);
    const uint32_t b2_base = sbase + W2_OFF +
        (uint32_t)((8 * w + (lane & 7)) * (K2P * 2) + (lane >> 3) * 16);
    const int crow = lane >> 2;
    const int sc   = (w >> 1) * 16 + (w & 1) * 8 + (lane & 3) * 2;

    for (int r = 0; r <= Tz; r++) {
        // ---- barrier: all slices finished round r-1 ----
        if (tid < NSLICE) {
            while (flag_acquire(&g_flag[grp][tid][0]) < base + 1ULL + (unsigned long long)r) { }
        }
        __syncthreads();

        // ---- cp.async h1(r-1), h2(r-2) tiles ----
        {
            const char* s1 = (const char*)&g_h1[grp][r & 1][0];
            const char* s2 = (const char*)&g_h2[grp][r & 1][0];
#pragma unroll
            for (int q = 0; q < 4; q++) {
                int z = q * 256 + tid;
                uint32_t off = (uint32_t)((z >> 6) * HROWB + (z & 63) * 16);
                cpa16(sbase + H1_OFF + off, s1 + z * 16);
                cpa16(sbase + H2_OFF + off, s2 + z * 16);
            }
            cpa_commit();
        }

        // ---- xp1 prefetch (t = r, clamped) ----
        const int tq = (r < Tz) ? r : (Tz - 1);
        const float* xb = xp + ((size_t)(grp * 16 + em) * Tz + tq) * Gz + gcol;
        float xq0 = __ldg(xb);
        float xq1 = __ldg(xb + 512);
        float xq2 = __ldg(xb + 1024);
        float xq3 = __ldg(xb + 1536);

        cpa_wait0();
        __syncthreads();

        // ---- MMA ----
        float c1_[4] = {0.f, 0.f, 0.f, 0.f};
        float c2_[4] = {0.f, 0.f, 0.f, 0.f};

        // part 1: A = h1(r-1); both layer-1 (wB1) and layer-2-ih (wB2) from regs
#pragma unroll
        for (int ks = 0; ks < 32; ks++) {
            uint32_t a0, a1, a2, a3;
            ldsm4(a0, a1, a2, a3, a1_base + (uint32_t)(ks * 32));
            mma16816(c1_, a0, a1, a2, a3, wB1[2 * ks], wB1[2 * ks + 1]);
            mma16816(c2_, a0, a1, a2, a3, wB2[2 * ks], wB2[2 * ks + 1]);
        }
        // part 2: A = h2(r-2); B = W_hh2 from SMEM (conflict-free stride)
#pragma unroll
        for (int ks2 = 0; ks2 < 16; ks2++) {
            uint32_t b0, b1, b2, b3;
            ldsm4(b0, b1, b2, b3, b2_base + (uint32_t)(ks2 * 64));
            uint32_t a0, a1, a2, a3;
            ldsm4(a0, a1, a2, a3, a2_base + (uint32_t)((2 * ks2) * 32));
            mma16816(c2_, a0, a1, a2, a3, b0, b1);
            ldsm4(a0, a1, a2, a3, a2_base + (uint32_t)((2 * ks2 + 1) * 32));
            mma16816(c2_, a0, a1, a2, a3, b2, b3);
        }

        // ---- stage gates ----
        gs1[crow * 80 + sc]           = c1_[0];
        gs1[crow * 80 + sc + 1]       = c1_[1];
        gs1[(crow + 8) * 80 + sc]     = c1_[2];
        gs1[(crow + 8) * 80 + sc + 1] = c1_[3];
        gs2[crow * 80 + sc]           = c2_[0];
        gs2[crow * 80 + sc + 1]       = c2_[1];
        gs2[(crow + 8) * 80 + sc]     = c2_[2];
        gs2[(crow + 8) * 80 + sc + 1] = c2_[3];
        __syncthreads();

        // ---- epilogues ----
        float h2v = 0.f;
        bool do2 = (r > 0);
        if (r < Tz) {
            float gi = gs1[em * 80 + col]      + xq0;
            float gf = gs1[em * 80 + 16 + col] + xq1;
            float gg = gs1[em * 80 + 32 + col] + xq2;
            float go = gs1[em * 80 + 48 + col] + xq3;
            float iv = sig_(gi), fv = sig_(gf), gv = tanh_(gg), ov = sig_(go);
            c1reg = fv * c1reg + iv * gv;
            float h1v = ov * tanh_(c1reg);
            g_h1[grp][(r + 1) & 1][em * Hz + gcol] = __float2half(h1v);
        }
        if (do2) {
            float gi = gs2[em * 80 + col]      + b2i;
            float gf = gs2[em * 80 + 16 + col] + b2f;
            float gg = gs2[em * 80 + 32 + col] + b2g;
            float go = gs2[em * 80 + 48 + col] + b2o;
            float iv = sig_(gi), fv = sig_(gf), gv = tanh_(gg), ov = sig_(go);
            c2reg = fv * c2reg + iv * gv;
            h2v = ov * tanh_(c2reg);
            g_h2[grp][(r + 1) & 1][em * Hz + gcol] = __float2half(h2v);
        }
        __syncthreads();
        if (tid == 0) flag_release(&g_flag[grp][n][0], base + 2ULL + (unsigned long long)r);
        if (do2)
            hseq[((size_t)(grp * 16 + em) * Tz + (r - 1)) * Hz + gcol] = h2v;
    }
}

// ---------------- final transpose: hseq [b][t][c] -> out [b][c][t] ----------
__global__ void __launch_bounds__(256)
transpose_out(const float* __restrict__ hseq, float* __restrict__ out)
{
    __shared__ float smt[32][33];
    const int t0 = blockIdx.x * 32;
    const int c0 = blockIdx.y * 32;
    const int b  = blockIdx.z;
    const int tx = threadIdx.x;
    const int ty = threadIdx.y;

#pragma unroll
    for (int i = 0; i < 4; i++)
        smt[ty + i * 8][tx] = hseq[((size_t)b * Tz + t0 + ty + i * 8) * Hz + c0 + tx];
    __syncthreads();
#pragma unroll
    for (int i = 0; i < 4; i++)
        out[(size_t)b * (Hz * Tz) + (size_t)(c0 + ty + i * 8) * Tz + t0 + tx] = smt[tx][ty + i * 8];
}

// ---------------- host launcher ----------------
extern "C" void kernel_launch(void* const* d_in, const int* in_sizes, int n_in,
                              void* d_out, int out_size)
{
    const float* x     = (const float*)d_in[0];
    const float* W_ih1 = (const float*)d_in[1];
    const float* W_hh1 = (const float*)d_in[2];
    const float* b_ih1 = (const float*)d_in[3];
    const float* b_hh1 = (const float*)d_in[4];
    const float* W_ih2 = (const float*)d_in[5];
    const float* W_hh2 = (const float*)d_in[6];
    const float* b_ih2 = (const float*)d_in[7];
    const float* b_hh2 = (const float*)d_in[8];
    float* out = (float*)d_out;

    float *p_xp, *p_hseq, *p_b1;
    __half *p_xh, *p_w16a, *p_w2img;
    uint32_t *p_wr1, *p_wr2;
    cudaGetSymbolAddress((void**)&p_xp,    g_xp);
    cudaGetSymbolAddress((void**)&p_hseq,  g_hseq);
    cudaGetSymbolAddress((void**)&p_xh,    g_xh);
    cudaGetSymbolAddress((void**)&p_w16a,  g_w16a);
    cudaGetSymbolAddress((void**)&p_b1,    g_bias1);
    cudaGetSymbolAddress((void**)&p_wr1,   g_wr1);
    cudaGetSymbolAddress((void**)&p_wr2,   g_wr2);
    cudaGetSymbolAddress((void**)&p_w2img, g_w2img);

    cudaFuncSetAttribute(lstm_rec2, cudaFuncAttributeMaxDynamicSharedMemorySize, REC_SMEM);

    // prep
    lstm_prep<<<(Gz * Cz + 255) / 256, 256>>>(W_ih1, b_ih1, b_hh1, b_ih2, b_hh2);
    prep_wr<<<(2 * NSLICE * 8 * 32 * 32 + 255) / 256, 256>>>(W_hh1, W_ih2);
    prep_w2img<<<(NSLICE * 64 * 512 + 255) / 256, 256>>>(W_hh2);
    convert_x<<<dim3(Tz / 32, Cz / 32, Bz), dim3(32, 8)>>>(x, p_xh);

    // xp1 = x16 @ W_ih1^T + bias1
    gemm_xp16<<<dim3(Gz / 128, Mz / 128), 256>>>(p_xh, p_w16a, p_b1, p_xp);

    // fused 2-layer recurrence -> g_hseq [m][c]
    lstm_rec2<<<NGRP * NSLICE, 256, REC_SMEM>>>(p_wr1, p_wr2, p_w2img, p_xp, p_hseq);

    // final transpose -> out (B, H, T)
    transpose_out<<<dim3(Tz / 32, Hz / 32, Bz), dim3(32, 8)>>>(p_hseq, out);
}